// round 14
// baseline (speedup 1.0000x reference)
#include <cuda_runtime.h>
#include <cuda_bf16.h>
#include <cstdint>

#define N_SPOT 30000
#define N_USER 30000
#define NE     600000
#define SPLIT  5
#define ATT_IN 512
#define HEADS  4
#define PER    128
#define HID    256
#define MPAD   30080   // 235 * 128

// ---------------- scratch (device globals; no allocation) ----------------
__device__ float g_wq[HEADS * ATT_IN];
__device__ float g_tmp_u[(size_t)N_USER * HID];
__device__ float g_tmp_s[(size_t)N_SPOT * HID];
__device__ float g_hs[3][(size_t)N_SPOT * HID];
__device__ float g_hu[3][(size_t)N_USER * HID];
__device__ float g_deg[4 * N_SPOT];
__device__ float g_rs[4 * N_SPOT];
__device__ int   g_off_us[N_SPOT + 1];
__device__ int   g_cur_us[N_SPOT];
__device__ int   g_csr_us[NE];
__device__ int   g_off_su[N_USER + 1];
__device__ int   g_cur_su[N_USER];
__device__ int   g_csr_su[NE];

// bf16 2-block split operands along K: [Ah | Al]  (row length = 2K)
__device__ __nv_bfloat16 g_A2att[(size_t)HEADS * MPAD * 1024];  // att: K=512
__device__ __nv_bfloat16 g_Au2[(size_t)MPAD * 1024];
__device__ __nv_bfloat16 g_As2[(size_t)MPAD * 1024];
// weights transposed [N][2K] as [Bh | Bl]
#define WOFF_ATT   0
#define WOFF_L0US  (4 * 128 * 1024)
#define WOFF_L0SU  (WOFF_L0US + 256 * 1024)
#define WOFF_MUS   (WOFF_L0SU + 256 * 1024)
#define WOFF_MSU   (WOFF_MUS + 2 * 256 * 512)
#define WTOT       (WOFF_MSU + 2 * 256 * 512)
__device__ __nv_bfloat16 g_B2[WTOT];

// ---------------- helpers ----------------
__device__ __forceinline__ uint32_t smem_u32(const void* p) {
    uint32_t r;
    asm("{ .reg .u64 t; cvta.to.shared.u64 t, %1; cvt.u32.u64 %0, t; }" : "=r"(r) : "l"(p));
    return r;
}
__device__ __forceinline__ void ldsm4(uint32_t addr, uint32_t& r0, uint32_t& r1,
                                      uint32_t& r2, uint32_t& r3) {
    asm volatile("ldmatrix.sync.aligned.m8n8.x4.shared.b16 {%0,%1,%2,%3}, [%4];"
                 : "=r"(r0), "=r"(r1), "=r"(r2), "=r"(r3) : "r"(addr));
}
__device__ __forceinline__ void mma16816(float* d, const uint32_t* a, const uint32_t* b) {
    asm volatile(
        "mma.sync.aligned.m16n8k16.row.col.f32.bf16.bf16.f32 "
        "{%0,%1,%2,%3}, {%4,%5,%6,%7}, {%8,%9}, {%0,%1,%2,%3};"
        : "+f"(d[0]), "+f"(d[1]), "+f"(d[2]), "+f"(d[3])
        : "r"(a[0]), "r"(a[1]), "r"(a[2]), "r"(a[3]), "r"(b[0]), "r"(b[1]));
}
#define CP16(dst, src) \
    asm volatile("cp.async.ca.shared.global [%0], [%1], 16;" :: "r"(dst), "l"(src))
#define CPCOMMIT() asm volatile("cp.async.commit_group;" ::: "memory")

// ---------------- degree / norm ----------------
__global__ void deg_count_kernel(const int* __restrict__ e_us, const int* __restrict__ e_su,
                                 float* __restrict__ deg) {
    int i = blockIdx.x * blockDim.x + threadIdx.x;
    if (i < NE) {
        atomicAdd(&deg[0 * N_SPOT + e_us[i]], 1.0f);
        atomicAdd(&deg[1 * N_SPOT + e_us[NE + i]], 1.0f);
        atomicAdd(&deg[2 * N_SPOT + e_su[i]], 1.0f);
        atomicAdd(&deg[3 * N_SPOT + e_su[NE + i]], 1.0f);
    }
}

__global__ void rsqrt_kernel(const float* __restrict__ deg, float* __restrict__ rs) {
    int i = blockIdx.x * blockDim.x + threadIdx.x;
    if (i < 4 * N_SPOT) {
        float d = deg[i];
        rs[i] = d > 0.f ? rsqrtf(d) : 0.f;
    }
}

// ---------------- CSR build ----------------
__global__ __launch_bounds__(1024) void scan2_kernel(const float* __restrict__ degall,
                                                     int* __restrict__ off_us, int* __restrict__ cur_us,
                                                     int* __restrict__ off_su, int* __restrict__ cur_su) {
    const float* deg = (blockIdx.x == 0) ? degall + 1 * N_SPOT : degall + 3 * N_SPOT;
    int* off = (blockIdx.x == 0) ? off_us : off_su;
    int* cur = (blockIdx.x == 0) ? cur_us : cur_su;
    const int n = N_SPOT;
    __shared__ int part[1024];
    const int t = threadIdx.x;
    const int CH = (n + 1023) / 1024;
    const int base = t * CH;
    int s = 0;
    for (int j = 0; j < CH; j++) {
        int idx = base + j;
        if (idx < n) s += (int)deg[idx];
    }
    part[t] = s;
    __syncthreads();
    for (int o = 1; o < 1024; o <<= 1) {
        int v = (t >= o) ? part[t - o] : 0;
        __syncthreads();
        part[t] += v;
        __syncthreads();
    }
    int run = t ? part[t - 1] : 0;
    for (int j = 0; j < CH; j++) {
        int idx = base + j;
        if (idx < n) {
            off[idx] = run;
            cur[idx] = run;
            run += (int)deg[idx];
        }
    }
    if (t == 0) off[n] = part[1023];
}

__global__ void fill_both_kernel(const int* __restrict__ e_us, const int* __restrict__ e_su,
                                 int* __restrict__ cur_us, int* __restrict__ csr_us,
                                 int* __restrict__ cur_su, int* __restrict__ csr_su) {
    int e = blockIdx.x * blockDim.x + threadIdx.x;
    if (e < NE) {
        int p = atomicAdd(&cur_us[e_us[NE + e]], 1);
        csr_us[p] = e_us[e];
        int q = atomicAdd(&cur_su[e_su[NE + e]], 1);
        csr_su[q] = e_su[e];
    }
}

// ---------------- all weight transposes+splits in one kernel ----------------
__device__ __forceinline__ void wsplit(const float* __restrict__ W, int K, int N,
                                       __nv_bfloat16* __restrict__ dst, int idx) {
    int n = idx / K, k = idx - n * K;
    float v = W[(size_t)k * N + n];
    __nv_bfloat16 h = __float2bfloat16(v);
    float r = v - __bfloat162float(h);
    size_t base = (size_t)n * 2 * K;
    dst[base + k] = h;
    dst[base + K + k] = __float2bfloat16(r);
}

__global__ void wprep_all_kernel(const float* __restrict__ W_att,
                                 const float* __restrict__ W0_us,
                                 const float* __restrict__ W0_su,
                                 const float* __restrict__ Wmid_us,
                                 const float* __restrict__ Wmid_su,
                                 __nv_bfloat16* __restrict__ B2) {
    long t = (long)blockIdx.x * 256 + threadIdx.x;
    const long E_ATT = 4L * 65536, E_L0 = 131072;
    if (t < E_ATT) {
        int h = (int)(t >> 16), r = (int)(t & 65535);
        wsplit(W_att + (size_t)h * 65536, 512, 128, B2 + WOFF_ATT + (size_t)h * 128 * 1024, r);
    } else if (t < E_ATT + E_L0) {
        wsplit(W0_us, 512, 256, B2 + WOFF_L0US, (int)(t - E_ATT));
    } else if (t < E_ATT + 2 * E_L0) {
        wsplit(W0_su, 512, 256, B2 + WOFF_L0SU, (int)(t - E_ATT - E_L0));
    } else {
        long u = t - E_ATT - 2 * E_L0;  // 4 x 65536: mus0, mus1, msu0, msu1
        int seg = (int)(u >> 16), r = (int)(u & 65535);
        int l = seg & 1;
        if (seg < 2)
            wsplit(Wmid_us + (size_t)l * 65536, 256, 256, B2 + WOFF_MUS + (size_t)l * 131072, r);
        else
            wsplit(Wmid_su + (size_t)l * 65536, 256, 256, B2 + WOFF_MSU + (size_t)l * 131072, r);
    }
}

// ---------------- fp32 -> A2[M][2K] = [Ah|Al] (layer-0 user, unscaled) ------------
__global__ void aconv_kernel(const float4* __restrict__ in, int M, int Kq, int Mpad,
                             __nv_bfloat162* __restrict__ out2) {
    int idx = blockIdx.x * 256 + threadIdx.x;
    if (idx >= Mpad * Kq) return;
    int row = idx / Kq, q = idx - row * Kq;
    const int K = Kq * 4;
    float4 v = make_float4(0.f, 0.f, 0.f, 0.f);
    if (row < M) v = in[idx];
    __nv_bfloat16 hx = __float2bfloat16(v.x), hy = __float2bfloat16(v.y);
    __nv_bfloat16 hz = __float2bfloat16(v.z), hw = __float2bfloat16(v.w);
    float rx = v.x - __bfloat162float(hx), ry = v.y - __bfloat162float(hy);
    float rz = v.z - __bfloat162float(hz), rw = v.w - __bfloat162float(hw);
    size_t b2 = (size_t)row * K;  // bf162 units per row = K
    out2[b2 + 2 * q + 0] = __nv_bfloat162(hx, hy);
    out2[b2 + 2 * q + 1] = __nv_bfloat162(hz, hw);
    out2[b2 + K / 2 + 2 * q + 0] = __nv_bfloat162(__float2bfloat16(rx), __float2bfloat16(ry));
    out2[b2 + K / 2 + 2 * q + 1] = __nv_bfloat162(__float2bfloat16(rz), __float2bfloat16(rw));
}

// ---------------- attention ----------------
__global__ void wq_kernel(const float* __restrict__ W, const float* __restrict__ q,
                          float* __restrict__ wq) {
    int t = blockIdx.x * blockDim.x + threadIdx.x;
    if (t >= HEADS * ATT_IN) return;
    int h = t / ATT_IN, i = t % ATT_IN;
    const float* w = W + ((size_t)h * ATT_IN + i) * PER;
    const float* qq = q + h * PER;
    float s = 0.f;
#pragma unroll 8
    for (int p = 0; p < PER; p++) s += w[p] * qq[p];
    wq[t] = s;
}

__global__ __launch_bounds__(128) void att_kernel(const float* __restrict__ x,
                                                  const float* __restrict__ wq,
                                                  __nv_bfloat16* __restrict__ A2) {
    int n = blockIdx.x;
    if (n >= N_SPOT) {
        uint4 z = make_uint4(0u, 0u, 0u, 0u);
#pragma unroll
        for (int h = 0; h < HEADS; h++) {
            uint4* dst = (uint4*)(A2 + ((size_t)h * MPAD + n) * 1024);
            dst[threadIdx.x] = z;
        }
        return;
    }
    __shared__ float sx[SPLIT * ATT_IN];
    __shared__ float satt[HEADS][SPLIT];
    const float4* xr4 = (const float4*)(x + (size_t)n * (SPLIT * ATT_IN));
#pragma unroll
    for (int j = 0; j < SPLIT; j++)
        ((float4*)sx)[threadIdx.x + 128 * j] = xr4[threadIdx.x + 128 * j];
    __syncthreads();

    int w = threadIdx.x >> 5, lane = threadIdx.x & 31;
    if (w < HEADS) {
        float lg[SPLIT];
#pragma unroll
        for (int s = 0; s < SPLIT; s++) {
            float p = 0.f;
            for (int i = lane; i < ATT_IN; i += 32) p += sx[s * ATT_IN + i] * wq[w * ATT_IN + i];
#pragma unroll
            for (int o = 16; o; o >>= 1) p += __shfl_down_sync(0xffffffffu, p, o);
            lg[s] = p;
        }
        if (lane == 0) {
            float mx = -1e30f;
#pragma unroll
            for (int s = 0; s < SPLIT; s++) {
                lg[s] = lg[s] >= 0.f ? lg[s] : 0.2f * lg[s];
                mx = fmaxf(mx, lg[s]);
            }
            float sum = 0.f;
#pragma unroll
            for (int s = 0; s < SPLIT; s++) { lg[s] = expf(lg[s] - mx); sum += lg[s]; }
            float r = 1.f / sum;
#pragma unroll
            for (int s = 0; s < SPLIT; s++) satt[w][s] = lg[s] * r;
        }
    }
    __syncthreads();

    const int i4 = threadIdx.x * 4;
#pragma unroll
    for (int h = 0; h < HEADS; h++) {
        float a0 = satt[h][0], a1 = satt[h][1], a2 = satt[h][2], a3 = satt[h][3], a4 = satt[h][4];
        float4 r0 = *(const float4*)&sx[0 * ATT_IN + i4];
        float4 r1 = *(const float4*)&sx[1 * ATT_IN + i4];
        float4 r2 = *(const float4*)&sx[2 * ATT_IN + i4];
        float4 r3 = *(const float4*)&sx[3 * ATT_IN + i4];
        float4 r4 = *(const float4*)&sx[4 * ATT_IN + i4];
        float y0 = a0 * r0.x + a1 * r1.x + a2 * r2.x + a3 * r3.x + a4 * r4.x;
        float y1 = a0 * r0.y + a1 * r1.y + a2 * r2.y + a3 * r3.y + a4 * r4.y;
        float y2 = a0 * r0.z + a1 * r1.z + a2 * r2.z + a3 * r3.z + a4 * r4.z;
        float y3 = a0 * r0.w + a1 * r1.w + a2 * r2.w + a3 * r3.w + a4 * r4.w;
        __nv_bfloat16 h0 = __float2bfloat16(y0), h1 = __float2bfloat16(y1);
        __nv_bfloat16 h2 = __float2bfloat16(y2), h3 = __float2bfloat16(y3);
        float l0 = y0 - __bfloat162float(h0), l1 = y1 - __bfloat162float(h1);
        float l2 = y2 - __bfloat162float(h2), l3 = y3 - __bfloat162float(h3);
        union { __nv_bfloat162 b[2]; uint2 u; } hv, lv;
        hv.b[0] = __nv_bfloat162(h0, h1); hv.b[1] = __nv_bfloat162(h2, h3);
        lv.b[0] = __nv_bfloat162(__float2bfloat16(l0), __float2bfloat16(l1));
        lv.b[1] = __nv_bfloat162(__float2bfloat16(l2), __float2bfloat16(l3));
        size_t base = ((size_t)h * MPAD + n) * 1024;
        *(uint2*)(A2 + base + i4) = hv.u;
        *(uint2*)(A2 + base + 512 + i4) = lv.u;
    }
}

// ---------------- bf16 HMMA GEMM: 4-tile k32 chunks, 3 products per chunk ----------------
// A stored [M][2K]=[Ah|Al], B stored [N][2K]=[Bh|Bl].
// Per k32 chunk: load Ah,Al,Bh,Bl tiles (128x32 each, 80B rows), compute
// Ah*Bh + Al*Bh + Ah*Bl into fp32 accumulators.
// SMEM/stage: 4 x 10240B = 40960B; 2 stages = 81920B -> 2 CTAs/SM.
// EPI=0: C fp32. EPI=1: split-bf16 out [hi|lo] (unscaled).
template <int EPI>
__global__ __launch_bounds__(256, 2) void hmma_gemm(
    const __nv_bfloat16* __restrict__ A2, int lda,
    const __nv_bfloat16* __restrict__ B2, int ldb,
    float* __restrict__ C, __nv_bfloat162* __restrict__ outb,
    int ldc, int M, int K,
    long sA, long sB, long sC) {
    extern __shared__ __align__(16) char smem[];
    uint32_t sb = smem_u32(smem);
    const int tid = threadIdx.x;
    const int wid = tid >> 5, lane = tid & 31;
    A2 += (long)blockIdx.z * sA;
    B2 += (long)blockIdx.z * sB;
    int col0 = 0;
    if (EPI == 0) C += (long)blockIdx.z * sC;
    else col0 = (int)((long)blockIdx.z * sC);
    const int m0 = blockIdx.x * 128;
    const int n0 = blockIdx.y * 128;
    const int wm = (wid & 3) * 32;
    const int wn = (wid >> 2) * 64;

    float acc[2][8][4];
#pragma unroll
    for (int i = 0; i < 2; i++)
#pragma unroll
        for (int j = 0; j < 8; j++)
#pragma unroll
            for (int v = 0; v < 4; v++) acc[i][j][v] = 0.f;

    // per-thread copy mapping: 8 cp16; tile = idx>>9 (0:Ah 1:Al 2:Bh 3:Bl)
#define COPY(buf, k0)                                                                     \
    {                                                                                     \
        _Pragma("unroll")                                                                 \
        for (int j = 0; j < 8; j++) {                                                     \
            int idx = tid + 256 * j;                                                      \
            int tile = idx >> 9;                                                          \
            int w_ = idx & 511;                                                           \
            int r = w_ >> 2, c = w_ & 3;                                                  \
            uint32_t dst = sb + (buf) * 40960 + tile * 10240 + r * 80 + c * 16;           \
            const __nv_bfloat16* src;                                                     \
            if (tile < 2)                                                                 \
                src = A2 + (size_t)(m0 + r) * lda + (tile == 1 ? K : 0) + (k0) + c * 8;   \
            else                                                                          \
                src = B2 + (size_t)(n0 + r) * ldb + (tile == 3 ? K : 0) + (k0) + c * 8;   \
            CP16(dst, src);                                                               \
        }                                                                                 \
        CPCOMMIT();                                                                       \
    }

    // one product: A tile (ta: 0 or 1) x B tile (tb: 2 or 3), k32 = 2 k16 steps
#define PROD(buf, ta, tb)                                                                 \
    {                                                                                     \
        uint32_t aBase = sb + (buf) * 40960 + (ta) * 10240;                               \
        uint32_t bBase = sb + (buf) * 40960 + (tb) * 10240;                               \
        _Pragma("unroll")                                                                 \
        for (int ks = 0; ks < 2; ks++) {                                                  \
            uint32_t af[2][4], bf[4][4];                                                  \
            int kb_ = ks * 32;                                                            \
            _Pragma("unroll")                                                             \
            for (int i = 0; i < 2; i++) {                                                 \
                uint32_t row = wm + i * 16 + (lane & 15);                                 \
                uint32_t addr = aBase + row * 80 + kb_ + (lane >> 4) * 16;                \
                ldsm4(addr, af[i][0], af[i][1], af[i][2], af[i][3]);                      \
            }                                                                             \
            _Pragma("unroll")                                                             \
            for (int j = 0; j < 4; j++) {                                                 \
                uint32_t g = lane >> 3, r8 = lane & 7;                                    \
                uint32_t row = wn + j * 16 + ((g >> 1) & 1) * 8 + r8;                     \
                uint32_t addr = bBase + row * 80 + kb_ + (g & 1) * 16;                    \
                ldsm4(addr, bf[j][0], bf[j][1], bf[j][2], bf[j][3]);                      \
            }                                                                             \
            _Pragma("unroll")                                                             \
            for (int i = 0; i < 2; i++)                                                   \
                _Pragma("unroll")                                                         \
                for (int j = 0; j < 4; j++) {                                             \
                    mma16816(acc[i][2 * j], af[i], &bf[j][0]);                            \
                    mma16816(acc[i][2 * j + 1], af[i], &bf[j][2]);                        \
                }                                                                         \
        }                                                                                 \
    }

    const int nch = K >> 5;
    COPY(0, 0);
    for (int ch = 0; ch < nch; ch++) {
        if (ch + 1 < nch) {
            COPY((ch + 1) & 1, (ch + 1) * 32);
            asm volatile("cp.async.wait_group 1;" ::: "memory");
        } else {
            asm volatile("cp.async.wait_group 0;" ::: "memory");
        }
        __syncthreads();
        PROD(ch & 1, 0, 2);  // Ah * Bh
        PROD(ch & 1, 1, 2);  // Al * Bh
        PROD(ch & 1, 0, 3);  // Ah * Bl
        __syncthreads();
    }

#pragma unroll
    for (int i = 0; i < 2; i++) {
#pragma unroll
        for (int j = 0; j < 8; j++) {
            int mA = m0 + wm + i * 16 + (lane >> 2);
            int col = n0 + wn + j * 8 + 2 * (lane & 3);
            if (EPI == 0) {
                if (mA < M) {
                    float2 v = make_float2(acc[i][j][0], acc[i][j][1]);
                    *(float2*)(C + (size_t)mA * ldc + col) = v;
                }
                if (mA + 8 < M) {
                    float2 v = make_float2(acc[i][j][2], acc[i][j][3]);
                    *(float2*)(C + (size_t)(mA + 8) * ldc + col) = v;
                }
            } else {
#pragma unroll
                for (int hh = 0; hh < 2; hh++) {
                    int m = mA + 8 * hh;
                    if (m < M) {
                        float v0 = acc[i][j][2 * hh];
                        float v1 = acc[i][j][2 * hh + 1];
                        __nv_bfloat16 h0 = __float2bfloat16(v0);
                        __nv_bfloat16 h1 = __float2bfloat16(v1);
                        float l0 = v0 - __bfloat162float(h0);
                        float l1 = v1 - __bfloat162float(h1);
                        size_t base = (size_t)m * ldc + col0 + col;
                        outb[base >> 1] = __nv_bfloat162(h0, h1);
                        outb[(base + (ldc >> 1)) >> 1] =
                            __nv_bfloat162(__float2bfloat16(l0), __float2bfloat16(l1));
                    }
                }
            }
        }
    }
#undef COPY
#undef PROD
}

// ---------------- merged CSR gather, fp32 msgs, per-edge src norm (+A2 emit) -------
__global__ __launch_bounds__(256) void gather_both_kernel(
    const float4* __restrict__ msg_u, const float4* __restrict__ msg_s,
    const int* __restrict__ off_us, const int* __restrict__ csr_us,
    const int* __restrict__ off_su, const int* __restrict__ csr_su,
    const float* __restrict__ rs,
    float4* __restrict__ out_s, float4* __restrict__ out_u,
    __nv_bfloat162* __restrict__ a2_s, __nv_bfloat162* __restrict__ a2_u, int emit) {
    int g = blockIdx.x * 4 + (threadIdx.x >> 6);
    int c = threadIdx.x & 63;
    const float4* msg;
    const int *off, *csr;
    const float *rd, *rsrc;
    float4* out;
    __nv_bfloat162* a2;
    int node;
    if (g < N_SPOT) {
        node = g;
        msg = msg_u; off = off_us; csr = csr_us;
        rd = rs + 1 * N_SPOT; rsrc = rs + 0 * N_SPOT;
        out = out_s; a2 = a2_s;
    } else {
        node = g - N_SPOT;
        if (node >= N_USER) return;
        msg = msg_s; off = off_su; csr = csr_su;
        rd = rs + 3 * N_SPOT; rsrc = rs + 2 * N_SPOT;
        out = out_u; a2 = a2_u;
    }
    int b = off[node], e = off[node + 1];
    float4 acc = make_float4(0.f, 0.f, 0.f, 0.f);
#define ACCUM(sid, wv)                                                   \
    {                                                                    \
        float4 v = __ldg(&msg[(size_t)(sid) * 64 + c]);                  \
        acc.x += v.x * (wv); acc.y += v.y * (wv);                        \
        acc.z += v.z * (wv); acc.w += v.w * (wv);                        \
    }
    int i = b;
    for (; i + 8 <= e; i += 8) {
        int s0 = __ldg(&csr[i]), s1 = __ldg(&csr[i + 1]);
        int s2 = __ldg(&csr[i + 2]), s3 = __ldg(&csr[i + 3]);
        int s4 = __ldg(&csr[i + 4]), s5 = __ldg(&csr[i + 5]);
        int s6 = __ldg(&csr[i + 6]), s7 = __ldg(&csr[i + 7]);
        float w0 = __ldg(&rsrc[s0]), w1 = __ldg(&rsrc[s1]);
        float w2 = __ldg(&rsrc[s2]), w3 = __ldg(&rsrc[s3]);
        float w4 = __ldg(&rsrc[s4]), w5 = __ldg(&rsrc[s5]);
        float w6 = __ldg(&rsrc[s6]), w7 = __ldg(&rsrc[s7]);
        ACCUM(s0, w0) ACCUM(s1, w1) ACCUM(s2, w2) ACCUM(s3, w3)
        ACCUM(s4, w4) ACCUM(s5, w5) ACCUM(s6, w6) ACCUM(s7, w7)
    }
    for (; i < e; i++) {
        int s0 = __ldg(&csr[i]);
        float w0 = __ldg(&rsrc[s0]);
        ACCUM(s0, w0)
    }
#undef ACCUM
    float sc = rd[node];
    acc.x *= sc; acc.y *= sc; acc.z *= sc; acc.w *= sc;
    out[(size_t)node * 64 + c] = acc;

    if (emit) {
        float vx = fmaxf(acc.x, 0.f), vy = fmaxf(acc.y, 0.f);
        float vz = fmaxf(acc.z, 0.f), vw = fmaxf(acc.w, 0.f);
        __nv_bfloat16 hx = __float2bfloat16(vx), hy = __float2bfloat16(vy);
        __nv_bfloat16 hz = __float2bfloat16(vz), hw = __float2bfloat16(vw);
        float rx = vx - __bfloat162float(hx), ry = vy - __bfloat162float(hy);
        float rz = vz - __bfloat162float(hz), rw = vw - __bfloat162float(hw);
        size_t bb = (size_t)node * 256 + 2 * c;
        a2[bb + 0] = __nv_bfloat162(hx, hy);
        a2[bb + 1] = __nv_bfloat162(hz, hw);
        a2[bb + 128 + 0] = __nv_bfloat162(__float2bfloat16(rx), __float2bfloat16(ry));
        a2[bb + 128 + 1] = __nv_bfloat162(__float2bfloat16(rz), __float2bfloat16(rw));
    }
}

// ---------------- outputs ----------------
__global__ void mean_kernel(const float* __restrict__ s0, const float* __restrict__ s1,
                            const float* __restrict__ s2,
                            const float* __restrict__ u0, const float* __restrict__ u1,
                            const float* __restrict__ u2,
                            float* __restrict__ out, int n) {
    int i = blockIdx.x * blockDim.x + threadIdx.x;
    if (i < n) {
        const float r = 1.f / 3.f;
        out[i] = (fmaxf(s0[i], 0.f) + fmaxf(s1[i], 0.f) + fmaxf(s2[i], 0.f)) * r;
        out[n + i] = (fmaxf(u0[i], 0.f) + fmaxf(u1[i], 0.f) + fmaxf(u2[i], 0.f)) * r;
    }
}

__global__ void out_head_kernel(const float* __restrict__ hs, const float* __restrict__ hu,
                                const float* __restrict__ Ws, const float* __restrict__ bs,
                                const float* __restrict__ Wu, const float* __restrict__ bu,
                                float* __restrict__ out_s, float* __restrict__ out_u) {
    int warp = (blockIdx.x * blockDim.x + threadIdx.x) >> 5;
    int lane = threadIdx.x & 31;
    if (warp < N_SPOT) {
        const float* x = hs + (size_t)warp * HID;
        float s = 0.f;
#pragma unroll
        for (int i = lane; i < HID; i += 32) s += fmaxf(x[i], 0.f) * Ws[i];
#pragma unroll
        for (int o = 16; o; o >>= 1) s += __shfl_down_sync(0xffffffffu, s, o);
        if (lane == 0) out_s[warp] = s + bs[0];
    } else if (warp < 2 * N_SPOT) {
        int n = warp - N_SPOT;
        const float* x = hu + (size_t)n * HID;
        float s = 0.f;
#pragma unroll
        for (int i = lane; i < HID; i += 32) s += fmaxf(x[i], 0.f) * Wu[i];
#pragma unroll
        for (int o = 16; o; o >>= 1) s += __shfl_down_sync(0xffffffffu, s, o);
        if (lane == 0) out_u[n] = s + bu[0];
    }
}

// ---------------- host ----------------
static float* sym_addr(const void* sym) {
    void* p = nullptr;
    cudaGetSymbolAddress(&p, sym);
    return (float*)p;
}
static int* sym_addr_i(const void* sym) {
    void* p = nullptr;
    cudaGetSymbolAddress(&p, sym);
    return (int*)p;
}
static __nv_bfloat16* sym_addr_b(const void* sym) {
    void* p = nullptr;
    cudaGetSymbolAddress(&p, sym);
    return (__nv_bfloat16*)p;
}

extern "C" void kernel_launch(void* const* d_in, const int* in_sizes, int n_in,
                              void* d_out, int out_size) {
    const float* x_spot  = (const float*)d_in[0];
    const float* x_user  = (const float*)d_in[1];
    const int*   edge_us = (const int*)d_in[2];
    const int*   edge_su = (const int*)d_in[3];
    const float* W_att   = (const float*)d_in[4];
    const float* q_att   = (const float*)d_in[5];
    const float* W0_us   = (const float*)d_in[6];
    const float* W0_su   = (const float*)d_in[7];
    const float* Wmid_us = (const float*)d_in[8];
    const float* Wmid_su = (const float*)d_in[9];
    const float* W_out_s = (const float*)d_in[10];
    const float* b_out_s = (const float*)d_in[11];
    const float* W_out_u = (const float*)d_in[12];
    const float* b_out_u = (const float*)d_in[13];
    float* out = (float*)d_out;

    float* p_wq    = sym_addr(g_wq);
    float* p_tmp_u = sym_addr(g_tmp_u);
    float* p_tmp_s = sym_addr(g_tmp_s);
    float* p_hs    = sym_addr(g_hs);
    float* p_hu    = sym_addr(g_hu);
    float* p_deg   = sym_addr(g_deg);
    float* p_rs    = sym_addr(g_rs);
    int* p_off_us  = sym_addr_i(g_off_us);
    int* p_cur_us  = sym_addr_i(g_cur_us);
    int* p_csr_us  = sym_addr_i(g_csr_us);
    int* p_off_su  = sym_addr_i(g_off_su);
    int* p_cur_su  = sym_addr_i(g_cur_su);
    int* p_csr_su  = sym_addr_i(g_csr_su);
    __nv_bfloat16* p_A2att = sym_addr_b(g_A2att);
    __nv_bfloat16* p_Au2   = sym_addr_b(g_Au2);
    __nv_bfloat16* p_As2   = sym_addr_b(g_As2);
    __nv_bfloat16* p_B2    = sym_addr_b(g_B2);

    const size_t HN = (size_t)N_SPOT * HID;
    const int NHID = N_SPOT * HID;
    const int SMEM = 2 * 40960;  // 81920
    cudaFuncSetAttribute(hmma_gemm<0>, cudaFuncAttributeMaxDynamicSharedMemorySize, SMEM);
    cudaFuncSetAttribute(hmma_gemm<1>, cudaFuncAttributeMaxDynamicSharedMemorySize, SMEM);

    const long sA_us = (long)(p_As2 - p_Au2);
    const long sC_us = (long)(p_tmp_s - p_tmp_u);
    int eb = (NE + 255) / 256;
    int gb2 = (2 * N_SPOT + 3) / 4;
    int rb = (NHID + 255) / 256;

    // 1: wq
    wq_kernel<<<(HEADS * ATT_IN + 255) / 256, 256>>>(W_att, q_att, p_wq);
    // 2: all weight splits
    wprep_all_kernel<<<3072, 256>>>(W_att, W0_us, W0_su, Wmid_us, Wmid_su, p_B2);
    // 3: attention pooling -> split A
    att_kernel<<<MPAD, 128>>>(x_spot, p_wq, p_A2att);
    // 4: attention GEMM (PROFILED SLOT) — writes layer-0 spot A operand (unscaled)
    hmma_gemm<1><<<dim3(MPAD / 128, 1, HEADS), 256, SMEM>>>(
        p_A2att, 1024, p_B2 + WOFF_ATT, 1024, nullptr,
        (__nv_bfloat162*)p_As2, 1024, N_SPOT, 512,
        (long)MPAD * 1024, (long)128 * 1024, 128);
    // deg clear + degrees + rs
    cudaMemsetAsync(p_deg, 0, 4 * N_SPOT * sizeof(float));
    deg_count_kernel<<<eb, 256>>>(edge_us, edge_su, p_deg);
    rsqrt_kernel<<<(4 * N_SPOT + 255) / 256, 256>>>(p_deg, p_rs);
    // CSR
    scan2_kernel<<<2, 1024>>>(p_deg, p_off_us, p_cur_us, p_off_su, p_cur_su);
    fill_both_kernel<<<eb, 256>>>(edge_us, edge_su, p_cur_us, p_csr_us, p_cur_su, p_csr_su);
    // layer-0 user A operand (unscaled)
    aconv_kernel<<<(MPAD * 128 + 255) / 256, 256>>>(
        (const float4*)x_user, N_USER, 128, MPAD, (__nv_bfloat162*)p_Au2);
    // layer-0 GEMMs merged (z=0 user, z=1 spot)
    hmma_gemm<0><<<dim3(MPAD / 128, 2, 2), 256, SMEM>>>(
        p_Au2, 1024, p_B2 + WOFF_L0US, 1024, p_tmp_u, nullptr,
        HID, N_SPOT, 512, sA_us, (long)(WOFF_L0SU - WOFF_L0US), sC_us);
    // gathers merged (per-edge src norm; emit next-layer A operands)
    gather_both_kernel<<<gb2, 256>>>(
        (const float4*)p_tmp_u, (const float4*)p_tmp_s,
        p_off_us, p_csr_us, p_off_su, p_csr_su, p_rs,
        (float4*)p_hs, (float4*)p_hu,
        (__nv_bfloat162*)p_As2, (__nv_bfloat162*)p_Au2, 1);

    // mid layers
    for (int l = 1; l < 3; l++) {
        float* hs_new = p_hs + l * HN;
        float* hu_new = p_hu + l * HN;
        bool last = (l == 2);
        hmma_gemm<0><<<dim3(MPAD / 128, 2, 2), 256, SMEM>>>(
            p_Au2, 512, p_B2 + WOFF_MUS + (l - 1) * 131072, 512, p_tmp_u, nullptr,
            HID, N_SPOT, 256, sA_us, (long)(WOFF_MSU - WOFF_MUS), sC_us);
        gather_both_kernel<<<gb2, 256>>>(
            (const float4*)p_tmp_u, (const float4*)p_tmp_s,
            p_off_us, p_csr_us, p_off_su, p_csr_su, p_rs,
            (float4*)hs_new, (float4*)hu_new,
            (__nv_bfloat162*)p_As2, (__nv_bfloat162*)p_Au2, last ? 0 : 1);
    }

    // outputs
    mean_kernel<<<rb, 256>>>(p_hs, p_hs + HN, p_hs + 2 * HN,
                             p_hu, p_hu + HN, p_hu + 2 * HN, out, NHID);
    out_head_kernel<<<(2 * N_SPOT * 32 + 255) / 256, 256>>>(
        p_hs + 2 * HN, p_hu + 2 * HN, W_out_s, b_out_s, W_out_u, b_out_u,
        out + 2 * (size_t)NHID, out + 2 * (size_t)NHID + N_SPOT);
}

// round 15
// speedup vs baseline: 1.0770x; 1.0770x over previous
#include <cuda_runtime.h>
#include <cuda_bf16.h>
#include <cstdint>

#define N_SPOT 30000
#define N_USER 30000
#define NE     600000
#define SPLIT  5
#define ATT_IN 512
#define HEADS  4
#define PER    128
#define HID    256
#define MPAD   30080   // 235 * 128

// ---------------- scratch (device globals; no allocation) ----------------
__device__ float g_wq[HEADS * ATT_IN];
__device__ float g_tmp_u[(size_t)N_USER * HID];
__device__ float g_tmp_s[(size_t)N_SPOT * HID];
__device__ float g_hs[3][(size_t)N_SPOT * HID];
__device__ float g_hu[3][(size_t)N_USER * HID];
__device__ float g_deg[4 * N_SPOT];
__device__ float g_rs[4 * N_SPOT];
__device__ int   g_off_us[N_SPOT + 1];
__device__ int   g_cur_us[N_SPOT];
__device__ int   g_csr_us[NE];
__device__ int   g_off_su[N_USER + 1];
__device__ int   g_cur_su[N_USER];
__device__ int   g_csr_su[NE];

// bf16 2-block split operands along K: [Ah | Al]  (row length = 2K)
__device__ __nv_bfloat16 g_A2att[(size_t)HEADS * MPAD * 1024];  // att: K=512
__device__ __nv_bfloat16 g_Au2[(size_t)MPAD * 1024];
__device__ __nv_bfloat16 g_As2[(size_t)MPAD * 1024];
// weights transposed [N][2K] as [Bh | Bl]
#define WOFF_ATT   0
#define WOFF_L0US  (4 * 128 * 1024)
#define WOFF_L0SU  (WOFF_L0US + 256 * 1024)
#define WOFF_MUS   (WOFF_L0SU + 256 * 1024)
#define WOFF_MSU   (WOFF_MUS + 2 * 256 * 512)
#define WTOT       (WOFF_MSU + 2 * 256 * 512)
__device__ __nv_bfloat16 g_B2[WTOT];

// ---------------- helpers ----------------
__device__ __forceinline__ uint32_t smem_u32(const void* p) {
    uint32_t r;
    asm("{ .reg .u64 t; cvta.to.shared.u64 t, %1; cvt.u32.u64 %0, t; }" : "=r"(r) : "l"(p));
    return r;
}
__device__ __forceinline__ void ldsm4(uint32_t addr, uint32_t& r0, uint32_t& r1,
                                      uint32_t& r2, uint32_t& r3) {
    asm volatile("ldmatrix.sync.aligned.m8n8.x4.shared.b16 {%0,%1,%2,%3}, [%4];"
                 : "=r"(r0), "=r"(r1), "=r"(r2), "=r"(r3) : "r"(addr));
}
__device__ __forceinline__ void mma16816(float* d, const uint32_t* a, const uint32_t* b) {
    asm volatile(
        "mma.sync.aligned.m16n8k16.row.col.f32.bf16.bf16.f32 "
        "{%0,%1,%2,%3}, {%4,%5,%6,%7}, {%8,%9}, {%0,%1,%2,%3};"
        : "+f"(d[0]), "+f"(d[1]), "+f"(d[2]), "+f"(d[3])
        : "r"(a[0]), "r"(a[1]), "r"(a[2]), "r"(a[3]), "r"(b[0]), "r"(b[1]));
}
#define CP16(dst, src) \
    asm volatile("cp.async.ca.shared.global [%0], [%1], 16;" :: "r"(dst), "l"(src))
#define CPCOMMIT() asm volatile("cp.async.commit_group;" ::: "memory")

// ---------------- degree / norm ----------------
__global__ void deg_count_kernel(const int* __restrict__ e_us, const int* __restrict__ e_su,
                                 float* __restrict__ deg) {
    int i = blockIdx.x * blockDim.x + threadIdx.x;
    if (i < NE) {
        atomicAdd(&deg[0 * N_SPOT + e_us[i]], 1.0f);
        atomicAdd(&deg[1 * N_SPOT + e_us[NE + i]], 1.0f);
        atomicAdd(&deg[2 * N_SPOT + e_su[i]], 1.0f);
        atomicAdd(&deg[3 * N_SPOT + e_su[NE + i]], 1.0f);
    }
}

__global__ void rsqrt_kernel(const float* __restrict__ deg, float* __restrict__ rs) {
    int i = blockIdx.x * blockDim.x + threadIdx.x;
    if (i < 4 * N_SPOT) {
        float d = deg[i];
        rs[i] = d > 0.f ? rsqrtf(d) : 0.f;
    }
}

// ---------------- CSR build ----------------
__global__ __launch_bounds__(1024) void scan2_kernel(const float* __restrict__ degall,
                                                     int* __restrict__ off_us, int* __restrict__ cur_us,
                                                     int* __restrict__ off_su, int* __restrict__ cur_su) {
    const float* deg = (blockIdx.x == 0) ? degall + 1 * N_SPOT : degall + 3 * N_SPOT;
    int* off = (blockIdx.x == 0) ? off_us : off_su;
    int* cur = (blockIdx.x == 0) ? cur_us : cur_su;
    const int n = N_SPOT;
    __shared__ int part[1024];
    const int t = threadIdx.x;
    const int CH = (n + 1023) / 1024;
    const int base = t * CH;
    int s = 0;
    for (int j = 0; j < CH; j++) {
        int idx = base + j;
        if (idx < n) s += (int)deg[idx];
    }
    part[t] = s;
    __syncthreads();
    for (int o = 1; o < 1024; o <<= 1) {
        int v = (t >= o) ? part[t - o] : 0;
        __syncthreads();
        part[t] += v;
        __syncthreads();
    }
    int run = t ? part[t - 1] : 0;
    for (int j = 0; j < CH; j++) {
        int idx = base + j;
        if (idx < n) {
            off[idx] = run;
            cur[idx] = run;
            run += (int)deg[idx];
        }
    }
    if (t == 0) off[n] = part[1023];
}

__global__ void fill_both_kernel(const int* __restrict__ e_us, const int* __restrict__ e_su,
                                 int* __restrict__ cur_us, int* __restrict__ csr_us,
                                 int* __restrict__ cur_su, int* __restrict__ csr_su) {
    int e = blockIdx.x * blockDim.x + threadIdx.x;
    if (e < NE) {
        int p = atomicAdd(&cur_us[e_us[NE + e]], 1);
        csr_us[p] = e_us[e];
        int q = atomicAdd(&cur_su[e_su[NE + e]], 1);
        csr_su[q] = e_su[e];
    }
}

// ---------------- all weight transposes+splits in one kernel ----------------
__device__ __forceinline__ void wsplit(const float* __restrict__ W, int K, int N,
                                       __nv_bfloat16* __restrict__ dst, int idx) {
    int n = idx / K, k = idx - n * K;
    float v = W[(size_t)k * N + n];
    __nv_bfloat16 h = __float2bfloat16(v);
    float r = v - __bfloat162float(h);
    size_t base = (size_t)n * 2 * K;
    dst[base + k] = h;
    dst[base + K + k] = __float2bfloat16(r);
}

__global__ void wprep_all_kernel(const float* __restrict__ W_att,
                                 const float* __restrict__ W0_us,
                                 const float* __restrict__ W0_su,
                                 const float* __restrict__ Wmid_us,
                                 const float* __restrict__ Wmid_su,
                                 __nv_bfloat16* __restrict__ B2) {
    long t = (long)blockIdx.x * 256 + threadIdx.x;
    const long E_ATT = 4L * 65536, E_L0 = 131072;
    if (t < E_ATT) {
        int h = (int)(t >> 16), r = (int)(t & 65535);
        wsplit(W_att + (size_t)h * 65536, 512, 128, B2 + WOFF_ATT + (size_t)h * 128 * 1024, r);
    } else if (t < E_ATT + E_L0) {
        wsplit(W0_us, 512, 256, B2 + WOFF_L0US, (int)(t - E_ATT));
    } else if (t < E_ATT + 2 * E_L0) {
        wsplit(W0_su, 512, 256, B2 + WOFF_L0SU, (int)(t - E_ATT - E_L0));
    } else {
        long u = t - E_ATT - 2 * E_L0;  // 4 x 65536: mus0, mus1, msu0, msu1
        int seg = (int)(u >> 16), r = (int)(u & 65535);
        int l = seg & 1;
        if (seg < 2)
            wsplit(Wmid_us + (size_t)l * 65536, 256, 256, B2 + WOFF_MUS + (size_t)l * 131072, r);
        else
            wsplit(Wmid_su + (size_t)l * 65536, 256, 256, B2 + WOFF_MSU + (size_t)l * 131072, r);
    }
}

// ---------------- fp32 -> A2[M][2K] = [Ah|Al] with row scale (layer-0 user) ------------
__global__ void aconv_kernel(const float4* __restrict__ in, const float* __restrict__ rs,
                             int M, int Kq, int Mpad,
                             __nv_bfloat162* __restrict__ out2) {
    int idx = blockIdx.x * 256 + threadIdx.x;
    if (idx >= Mpad * Kq) return;
    int row = idx / Kq, q = idx - row * Kq;
    const int K = Kq * 4;
    float4 v = make_float4(0.f, 0.f, 0.f, 0.f);
    if (row < M) {
        v = in[idx];
        float sc = rs[row];
        v.x *= sc; v.y *= sc; v.z *= sc; v.w *= sc;
    }
    __nv_bfloat16 hx = __float2bfloat16(v.x), hy = __float2bfloat16(v.y);
    __nv_bfloat16 hz = __float2bfloat16(v.z), hw = __float2bfloat16(v.w);
    float rx = v.x - __bfloat162float(hx), ry = v.y - __bfloat162float(hy);
    float rz = v.z - __bfloat162float(hz), rw = v.w - __bfloat162float(hw);
    size_t b2 = (size_t)row * K;  // bf162 units per row = K
    out2[b2 + 2 * q + 0] = __nv_bfloat162(hx, hy);
    out2[b2 + 2 * q + 1] = __nv_bfloat162(hz, hw);
    out2[b2 + K / 2 + 2 * q + 0] = __nv_bfloat162(__float2bfloat16(rx), __float2bfloat16(ry));
    out2[b2 + K / 2 + 2 * q + 1] = __nv_bfloat162(__float2bfloat16(rz), __float2bfloat16(rw));
}

// ---------------- attention ----------------
__global__ void wq_kernel(const float* __restrict__ W, const float* __restrict__ q,
                          float* __restrict__ wq) {
    int t = blockIdx.x * blockDim.x + threadIdx.x;
    if (t >= HEADS * ATT_IN) return;
    int h = t / ATT_IN, i = t % ATT_IN;
    const float* w = W + ((size_t)h * ATT_IN + i) * PER;
    const float* qq = q + h * PER;
    float s = 0.f;
#pragma unroll 8
    for (int p = 0; p < PER; p++) s += w[p] * qq[p];
    wq[t] = s;
}

// per node: softmax pooling; emits [hi(512) | lo(512)] per head row. Vectorized.
// Pad rows (>= N_SPOT) skipped: device globals are zero-initialized and EPI
// guards discard pad outputs, so they stay zero across replays.
__global__ __launch_bounds__(128) void att_kernel(const float* __restrict__ x,
                                                  const float* __restrict__ wq,
                                                  __nv_bfloat16* __restrict__ A2) {
    int n = blockIdx.x;
    __shared__ float sx[SPLIT * ATT_IN];
    __shared__ float satt[HEADS][SPLIT];
    const float4* xr4 = (const float4*)(x + (size_t)n * (SPLIT * ATT_IN));
#pragma unroll
    for (int j = 0; j < SPLIT; j++)
        ((float4*)sx)[threadIdx.x + 128 * j] = xr4[threadIdx.x + 128 * j];
    __syncthreads();

    int w = threadIdx.x >> 5, lane = threadIdx.x & 31;
    if (w < HEADS) {
        float lg[SPLIT];
#pragma unroll
        for (int s = 0; s < SPLIT; s++) {
            float p = 0.f;
            for (int i = lane; i < ATT_IN; i += 32) p += sx[s * ATT_IN + i] * wq[w * ATT_IN + i];
#pragma unroll
            for (int o = 16; o; o >>= 1) p += __shfl_down_sync(0xffffffffu, p, o);
            lg[s] = p;
        }
        if (lane == 0) {
            float mx = -1e30f;
#pragma unroll
            for (int s = 0; s < SPLIT; s++) {
                lg[s] = lg[s] >= 0.f ? lg[s] : 0.2f * lg[s];
                mx = fmaxf(mx, lg[s]);
            }
            float sum = 0.f;
#pragma unroll
            for (int s = 0; s < SPLIT; s++) { lg[s] = expf(lg[s] - mx); sum += lg[s]; }
            float r = 1.f / sum;
#pragma unroll
            for (int s = 0; s < SPLIT; s++) satt[w][s] = lg[s] * r;
        }
    }
    __syncthreads();

    const int i4 = threadIdx.x * 4;
#pragma unroll
    for (int h = 0; h < HEADS; h++) {
        float a0 = satt[h][0], a1 = satt[h][1], a2 = satt[h][2], a3 = satt[h][3], a4 = satt[h][4];
        float4 r0 = *(const float4*)&sx[0 * ATT_IN + i4];
        float4 r1 = *(const float4*)&sx[1 * ATT_IN + i4];
        float4 r2 = *(const float4*)&sx[2 * ATT_IN + i4];
        float4 r3 = *(const float4*)&sx[3 * ATT_IN + i4];
        float4 r4 = *(const float4*)&sx[4 * ATT_IN + i4];
        float y0 = a0 * r0.x + a1 * r1.x + a2 * r2.x + a3 * r3.x + a4 * r4.x;
        float y1 = a0 * r0.y + a1 * r1.y + a2 * r2.y + a3 * r3.y + a4 * r4.y;
        float y2 = a0 * r0.z + a1 * r1.z + a2 * r2.z + a3 * r3.z + a4 * r4.z;
        float y3 = a0 * r0.w + a1 * r1.w + a2 * r2.w + a3 * r3.w + a4 * r4.w;
        __nv_bfloat16 h0 = __float2bfloat16(y0), h1 = __float2bfloat16(y1);
        __nv_bfloat16 h2 = __float2bfloat16(y2), h3 = __float2bfloat16(y3);
        float l0 = y0 - __bfloat162float(h0), l1 = y1 - __bfloat162float(h1);
        float l2 = y2 - __bfloat162float(h2), l3 = y3 - __bfloat162float(h3);
        union { __nv_bfloat162 b[2]; uint2 u; } hv, lv;
        hv.b[0] = __nv_bfloat162(h0, h1); hv.b[1] = __nv_bfloat162(h2, h3);
        lv.b[0] = __nv_bfloat162(__float2bfloat16(l0), __float2bfloat16(l1));
        lv.b[1] = __nv_bfloat162(__float2bfloat16(l2), __float2bfloat16(l3));
        size_t base = ((size_t)h * MPAD + n) * 1024;
        *(uint2*)(A2 + base + i4) = hv.u;
        *(uint2*)(A2 + base + 512 + i4) = lv.u;
    }
}

// ---------------- bf16 HMMA GEMM, 2-stage cp.async pipeline, 3-product split ----------------
// (round-12 proven configuration)
// A stored [M][2K]=[Ah|Al], B stored [N][2K]=[Bh|Bl].
// Per 64-wide K slice: Ah*Bh, Al*Bh, Ah*Bl.
// EPI=0: C fp32. EPI=1: split-bf16 out [hi|lo], scaled rs[m].
#define STG 2
template <int EPI>
__global__ __launch_bounds__(256, 2) void hmma_gemm(
    const __nv_bfloat16* __restrict__ A2, int lda,
    const __nv_bfloat16* __restrict__ B2, int ldb,
    float* __restrict__ C, __nv_bfloat162* __restrict__ outb,
    const float* __restrict__ rsp,
    int ldc, int M, int K,
    long sA, long sB, long sC) {
    extern __shared__ __align__(16) char smem[];
    uint32_t sb = smem_u32(smem);
    const int tid = threadIdx.x;
    const int wid = tid >> 5, lane = tid & 31;
    A2 += (long)blockIdx.z * sA;
    B2 += (long)blockIdx.z * sB;
    int col0 = 0;
    if (EPI == 0) C += (long)blockIdx.z * sC;
    else col0 = (int)((long)blockIdx.z * sC);
    const int m0 = blockIdx.x * 128;
    const int n0 = blockIdx.y * 128;
    const int wm = (wid & 3) * 32;
    const int wn = (wid >> 2) * 64;

    float acc[2][8][4];
#pragma unroll
    for (int i = 0; i < 2; i++)
#pragma unroll
        for (int j = 0; j < 8; j++)
#pragma unroll
            for (int v = 0; v < 4; v++) acc[i][j][v] = 0.f;

#define OFFS(ch, ka, kb)                                   \
    {                                                      \
        int bq = (ch) / 3, br_ = (ch) - 3 * bq;            \
        ka = bq * 64 + (br_ == 1 ? K : 0);                 \
        kb = bq * 64 + (br_ == 2 ? K : 0);                 \
    }

#define COPY(buf, ka, kb)                                                                 \
    {                                                                                     \
        _Pragma("unroll")                                                                 \
        for (int j = 0; j < 4; j++) {                                                     \
            int idx = tid + 256 * j;                                                      \
            int r = idx >> 3, c = idx & 7;                                                \
            uint32_t da = sb + (buf) * 36864 + r * 144 + c * 16;                          \
            CP16(da, A2 + (size_t)(m0 + r) * lda + (ka) + c * 8);                         \
            CP16(da + 18432, B2 + (size_t)(n0 + r) * ldb + (kb) + c * 8);                 \
        }                                                                                 \
        CPCOMMIT();                                                                       \
    }

#define COMPUTE(buf)                                                                      \
    {                                                                                     \
        uint32_t aBase = sb + (buf) * 36864;                                              \
        uint32_t bBase = aBase + 18432;                                                   \
        _Pragma("unroll")                                                                 \
        for (int ks = 0; ks < 4; ks++) {                                                  \
            uint32_t af[2][4], bf[4][4];                                                  \
            int kb_ = ks * 32;                                                            \
            _Pragma("unroll")                                                             \
            for (int i = 0; i < 2; i++) {                                                 \
                uint32_t row = wm + i * 16 + (lane & 15);                                 \
                uint32_t addr = aBase + row * 144 + kb_ + (lane >> 4) * 16;               \
                ldsm4(addr, af[i][0], af[i][1], af[i][2], af[i][3]);                      \
            }                                                                             \
            _Pragma("unroll")                                                             \
            for (int j = 0; j < 4; j++) {                                                 \
                uint32_t g = lane >> 3, r8 = lane & 7;                                    \
                uint32_t row = wn + j * 16 + ((g >> 1) & 1) * 8 + r8;                     \
                uint32_t addr = bBase + row * 144 + kb_ + (g & 1) * 16;                   \
                ldsm4(addr, bf[j][0], bf[j][1], bf[j][2], bf[j][3]);                      \
            }                                                                             \
            _Pragma("unroll")                                                             \
            for (int i = 0; i < 2; i++)                                                   \
                _Pragma("unroll")                                                         \
                for (int j = 0; j < 4; j++) {                                             \
                    mma16816(acc[i][2 * j], af[i], &bf[j][0]);                            \
                    mma16816(acc[i][2 * j + 1], af[i], &bf[j][2]);                        \
                }                                                                         \
        }                                                                                 \
    }

    const int nch = 3 * (K >> 6);
    {
        int ka, kb;
        OFFS(0, ka, kb);
        COPY(0, ka, kb);
    }
    for (int ch = 0; ch < nch; ch++) {
        if (ch + 1 < nch) {
            int ka, kb;
            OFFS(ch + 1, ka, kb);
            COPY((ch + 1) & 1, ka, kb);
            asm volatile("cp.async.wait_group 1;" ::: "memory");
        } else {
            asm volatile("cp.async.wait_group 0;" ::: "memory");
        }
        __syncthreads();
        COMPUTE(ch & 1);
        __syncthreads();
    }

#pragma unroll
    for (int i = 0; i < 2; i++) {
#pragma unroll
        for (int j = 0; j < 8; j++) {
            int mA = m0 + wm + i * 16 + (lane >> 2);
            int col = n0 + wn + j * 8 + 2 * (lane & 3);
            if (EPI == 0) {
                if (mA < M) {
                    float2 v = make_float2(acc[i][j][0], acc[i][j][1]);
                    *(float2*)(C + (size_t)mA * ldc + col) = v;
                }
                if (mA + 8 < M) {
                    float2 v = make_float2(acc[i][j][2], acc[i][j][3]);
                    *(float2*)(C + (size_t)(mA + 8) * ldc + col) = v;
                }
            } else {
#pragma unroll
                for (int hh = 0; hh < 2; hh++) {
                    int m = mA + 8 * hh;
                    if (m < M) {
                        float sc = rsp[m];
                        float v0 = acc[i][j][2 * hh] * sc;
                        float v1 = acc[i][j][2 * hh + 1] * sc;
                        __nv_bfloat16 h0 = __float2bfloat16(v0);
                        __nv_bfloat16 h1 = __float2bfloat16(v1);
                        float l0 = v0 - __bfloat162float(h0);
                        float l1 = v1 - __bfloat162float(h1);
                        size_t base = (size_t)m * ldc + col0 + col;
                        outb[base >> 1] = __nv_bfloat162(h0, h1);
                        outb[(base + (ldc >> 1)) >> 1] =
                            __nv_bfloat162(__float2bfloat16(l0), __float2bfloat16(l1));
                    }
                }
            }
        }
    }
#undef OFFS
#undef COPY
#undef COMPUTE
}

// ---------------- merged CSR gather (fp32 msgs, dst norm + next-layer emit) --------
__global__ __launch_bounds__(256) void gather_both_kernel(
    const float4* __restrict__ msg_u, const float4* __restrict__ msg_s,
    const int* __restrict__ off_us, const int* __restrict__ csr_us,
    const int* __restrict__ off_su, const int* __restrict__ csr_su,
    const float* __restrict__ rs,
    float4* __restrict__ out_s, float4* __restrict__ out_u,
    __nv_bfloat162* __restrict__ a2_s, __nv_bfloat162* __restrict__ a2_u, int emit) {
    int g = blockIdx.x * 4 + (threadIdx.x >> 6);
    int c = threadIdx.x & 63;
    const float4* msg;
    const int *off, *csr;
    const float *rd, *rsn;
    float4* out;
    __nv_bfloat162* a2;
    int node;
    if (g < N_SPOT) {
        node = g;
        msg = msg_u; off = off_us; csr = csr_us;
        rd = rs + 1 * N_SPOT; rsn = rs + 2 * N_SPOT;  // dst=spot; next-layer src=spot
        out = out_s; a2 = a2_s;
    } else {
        node = g - N_SPOT;
        if (node >= N_USER) return;
        msg = msg_s; off = off_su; csr = csr_su;
        rd = rs + 3 * N_SPOT; rsn = rs + 0 * N_SPOT;  // dst=user; next-layer src=user
        out = out_u; a2 = a2_u;
    }
    int b = off[node], e = off[node + 1];
    float4 acc = make_float4(0.f, 0.f, 0.f, 0.f);
#define ACCUM(sid)                                                       \
    {                                                                    \
        float4 v = __ldg(&msg[(size_t)(sid) * 64 + c]);                  \
        acc.x += v.x; acc.y += v.y; acc.z += v.z; acc.w += v.w;          \
    }
    int i = b;
    for (; i + 8 <= e; i += 8) {
        int s0 = __ldg(&csr[i]), s1 = __ldg(&csr[i + 1]);
        int s2 = __ldg(&csr[i + 2]), s3 = __ldg(&csr[i + 3]);
        int s4 = __ldg(&csr[i + 4]), s5 = __ldg(&csr[i + 5]);
        int s6 = __ldg(&csr[i + 6]), s7 = __ldg(&csr[i + 7]);
        ACCUM(s0) ACCUM(s1) ACCUM(s2) ACCUM(s3)
        ACCUM(s4) ACCUM(s5) ACCUM(s6) ACCUM(s7)
    }
    for (; i < e; i++) {
        int s0 = __ldg(&csr[i]);
        ACCUM(s0)
    }
#undef ACCUM
    float sc = rd[node];
    acc.x *= sc; acc.y *= sc; acc.z *= sc; acc.w *= sc;
    out[(size_t)node * 64 + c] = acc;

    if (emit) {
        float s2c = rsn[node];
        float vx = fmaxf(acc.x, 0.f) * s2c, vy = fmaxf(acc.y, 0.f) * s2c;
        float vz = fmaxf(acc.z, 0.f) * s2c, vw = fmaxf(acc.w, 0.f) * s2c;
        __nv_bfloat16 hx = __float2bfloat16(vx), hy = __float2bfloat16(vy);
        __nv_bfloat16 hz = __float2bfloat16(vz), hw = __float2bfloat16(vw);
        float rx = vx - __bfloat162float(hx), ry = vy - __bfloat162float(hy);
        float rz = vz - __bfloat162float(hz), rw = vw - __bfloat162float(hw);
        size_t bb = (size_t)node * 256 + 2 * c;
        a2[bb + 0] = __nv_bfloat162(hx, hy);
        a2[bb + 1] = __nv_bfloat162(hz, hw);
        a2[bb + 128 + 0] = __nv_bfloat162(__float2bfloat16(rx), __float2bfloat16(ry));
        a2[bb + 128 + 1] = __nv_bfloat162(__float2bfloat16(rz), __float2bfloat16(rw));
    }
}

// ---------------- outputs ----------------
__global__ void mean_kernel(const float4* __restrict__ s0, const float4* __restrict__ s1,
                            const float4* __restrict__ s2,
                            const float4* __restrict__ u0, const float4* __restrict__ u1,
                            const float4* __restrict__ u2,
                            float4* __restrict__ out, int n4) {
    int i = blockIdx.x * blockDim.x + threadIdx.x;
    if (i < n4) {
        const float r = 1.f / 3.f;
        float4 a = s0[i], b = s1[i], c = s2[i];
        float4 o;
        o.x = (fmaxf(a.x, 0.f) + fmaxf(b.x, 0.f) + fmaxf(c.x, 0.f)) * r;
        o.y = (fmaxf(a.y, 0.f) + fmaxf(b.y, 0.f) + fmaxf(c.y, 0.f)) * r;
        o.z = (fmaxf(a.z, 0.f) + fmaxf(b.z, 0.f) + fmaxf(c.z, 0.f)) * r;
        o.w = (fmaxf(a.w, 0.f) + fmaxf(b.w, 0.f) + fmaxf(c.w, 0.f)) * r;
        out[i] = o;
        a = u0[i]; b = u1[i]; c = u2[i];
        o.x = (fmaxf(a.x, 0.f) + fmaxf(b.x, 0.f) + fmaxf(c.x, 0.f)) * r;
        o.y = (fmaxf(a.y, 0.f) + fmaxf(b.y, 0.f) + fmaxf(c.y, 0.f)) * r;
        o.z = (fmaxf(a.z, 0.f) + fmaxf(b.z, 0.f) + fmaxf(c.z, 0.f)) * r;
        o.w = (fmaxf(a.w, 0.f) + fmaxf(b.w, 0.f) + fmaxf(c.w, 0.f)) * r;
        out[n4 + i] = o;
    }
}

__global__ void out_head_kernel(const float* __restrict__ hs, const float* __restrict__ hu,
                                const float* __restrict__ Ws, const float* __restrict__ bs,
                                const float* __restrict__ Wu, const float* __restrict__ bu,
                                float* __restrict__ out_s, float* __restrict__ out_u) {
    int warp = (blockIdx.x * blockDim.x + threadIdx.x) >> 5;
    int lane = threadIdx.x & 31;
    if (warp < N_SPOT) {
        const float* x = hs + (size_t)warp * HID;
        float s = 0.f;
#pragma unroll
        for (int i = lane; i < HID; i += 32) s += fmaxf(x[i], 0.f) * Ws[i];
#pragma unroll
        for (int o = 16; o; o >>= 1) s += __shfl_down_sync(0xffffffffu, s, o);
        if (lane == 0) out_s[warp] = s + bs[0];
    } else if (warp < 2 * N_SPOT) {
        int n = warp - N_SPOT;
        const float* x = hu + (size_t)n * HID;
        float s = 0.f;
#pragma unroll
        for (int i = lane; i < HID; i += 32) s += fmaxf(x[i], 0.f) * Wu[i];
#pragma unroll
        for (int o = 16; o; o >>= 1) s += __shfl_down_sync(0xffffffffu, s, o);
        if (lane == 0) out_u[n] = s + bu[0];
    }
}

// ---------------- host ----------------
static float* sym_addr(const void* sym) {
    void* p = nullptr;
    cudaGetSymbolAddress(&p, sym);
    return (float*)p;
}
static int* sym_addr_i(const void* sym) {
    void* p = nullptr;
    cudaGetSymbolAddress(&p, sym);
    return (int*)p;
}
static __nv_bfloat16* sym_addr_b(const void* sym) {
    void* p = nullptr;
    cudaGetSymbolAddress(&p, sym);
    return (__nv_bfloat16*)p;
}

extern "C" void kernel_launch(void* const* d_in, const int* in_sizes, int n_in,
                              void* d_out, int out_size) {
    const float* x_spot  = (const float*)d_in[0];
    const float* x_user  = (const float*)d_in[1];
    const int*   edge_us = (const int*)d_in[2];
    const int*   edge_su = (const int*)d_in[3];
    const float* W_att   = (const float*)d_in[4];
    const float* q_att   = (const float*)d_in[5];
    const float* W0_us   = (const float*)d_in[6];
    const float* W0_su   = (const float*)d_in[7];
    const float* Wmid_us = (const float*)d_in[8];
    const float* Wmid_su = (const float*)d_in[9];
    const float* W_out_s = (const float*)d_in[10];
    const float* b_out_s = (const float*)d_in[11];
    const float* W_out_u = (const float*)d_in[12];
    const float* b_out_u = (const float*)d_in[13];
    float* out = (float*)d_out;

    float* p_wq    = sym_addr(g_wq);
    float* p_tmp_u = sym_addr(g_tmp_u);
    float* p_tmp_s = sym_addr(g_tmp_s);
    float* p_hs    = sym_addr(g_hs);
    float* p_hu    = sym_addr(g_hu);
    float* p_deg   = sym_addr(g_deg);
    float* p_rs    = sym_addr(g_rs);
    int* p_off_us  = sym_addr_i(g_off_us);
    int* p_cur_us  = sym_addr_i(g_cur_us);
    int* p_csr_us  = sym_addr_i(g_csr_us);
    int* p_off_su  = sym_addr_i(g_off_su);
    int* p_cur_su  = sym_addr_i(g_cur_su);
    int* p_csr_su  = sym_addr_i(g_csr_su);
    __nv_bfloat16* p_A2att = sym_addr_b(g_A2att);
    __nv_bfloat16* p_Au2   = sym_addr_b(g_Au2);
    __nv_bfloat16* p_As2   = sym_addr_b(g_As2);
    __nv_bfloat16* p_B2    = sym_addr_b(g_B2);

    const size_t HN = (size_t)N_SPOT * HID;
    const int NHID = N_SPOT * HID;
    const int SMEM = STG * 36864;  // 73728
    cudaFuncSetAttribute(hmma_gemm<0>, cudaFuncAttributeMaxDynamicSharedMemorySize, SMEM);
    cudaFuncSetAttribute(hmma_gemm<1>, cudaFuncAttributeMaxDynamicSharedMemorySize, SMEM);

    const long sA_us = (long)(p_As2 - p_Au2);
    const long sC_us = (long)(p_tmp_s - p_tmp_u);
    int eb = (NE + 255) / 256;
    int gb2 = (2 * N_SPOT + 3) / 4;
    int rb = (NHID / 4 + 255) / 256;

    // 1: wq
    wq_kernel<<<(HEADS * ATT_IN + 255) / 256, 256>>>(W_att, q_att, p_wq);
    // 2: all weight splits
    wprep_all_kernel<<<3072, 256>>>(W_att, W0_us, W0_su, Wmid_us, Wmid_su, p_B2);
    // 3: attention pooling -> split A  (only real rows; pads stay zero)
    att_kernel<<<N_SPOT, 128>>>(x_spot, p_wq, p_A2att);
    // deg clear + degrees + rs (needed by att GEMM epilogue)
    cudaMemsetAsync(p_deg, 0, 4 * N_SPOT * sizeof(float));
    // 4-5: degrees + rs
    deg_count_kernel<<<eb, 256>>>(edge_us, edge_su, p_deg);
    rsqrt_kernel<<<(4 * N_SPOT + 255) / 256, 256>>>(p_deg, p_rs);
    // 6: attention GEMM — writes layer-0 spot A operand (scaled by spot src norm)
    hmma_gemm<1><<<dim3(MPAD / 128, 1, HEADS), 256, SMEM>>>(
        p_A2att, 1024, p_B2 + WOFF_ATT, 1024, nullptr,
        (__nv_bfloat162*)p_As2, p_rs + 2 * N_SPOT,
        1024, N_SPOT, 512,
        (long)MPAD * 1024, (long)128 * 1024, 128);
    // CSR
    scan2_kernel<<<2, 1024>>>(p_deg, p_off_us, p_cur_us, p_off_su, p_cur_su);
    fill_both_kernel<<<eb, 256>>>(edge_us, edge_su, p_cur_us, p_csr_us, p_cur_su, p_csr_su);
    // layer-0 user A operand (scaled by user src norm)
    aconv_kernel<<<(MPAD * 128 + 255) / 256, 256>>>(
        (const float4*)x_user, p_rs + 0 * N_SPOT, N_USER, 128, MPAD,
        (__nv_bfloat162*)p_Au2);
    // layer-0 GEMMs merged (z=0 user, z=1 spot)
    hmma_gemm<0><<<dim3(MPAD / 128, 2, 2), 256, SMEM>>>(
        p_Au2, 1024, p_B2 + WOFF_L0US, 1024, p_tmp_u, nullptr, nullptr,
        HID, N_SPOT, 512, sA_us, (long)(WOFF_L0SU - WOFF_L0US), sC_us);
    // gathers merged (dst norm; emit next-layer A operands with src norm)
    gather_both_kernel<<<gb2, 256>>>(
        (const float4*)p_tmp_u, (const float4*)p_tmp_s,
        p_off_us, p_csr_us, p_off_su, p_csr_su, p_rs,
        (float4*)p_hs, (float4*)p_hu,
        (__nv_bfloat162*)p_As2, (__nv_bfloat162*)p_Au2, 1);

    // mid layers
    for (int l = 1; l < 3; l++) {
        float* hs_new = p_hs + l * HN;
        float* hu_new = p_hu + l * HN;
        bool last = (l == 2);
        hmma_gemm<0><<<dim3(MPAD / 128, 2, 2), 256, SMEM>>>(
            p_Au2, 512, p_B2 + WOFF_MUS + (l - 1) * 131072, 512, p_tmp_u, nullptr, nullptr,
            HID, N_SPOT, 256, sA_us, (long)(WOFF_MSU - WOFF_MUS), sC_us);
        gather_both_kernel<<<gb2, 256>>>(
            (const float4*)p_tmp_u, (const float4*)p_tmp_s,
            p_off_us, p_csr_us, p_off_su, p_csr_su, p_rs,
            (float4*)hs_new, (float4*)hu_new,
            (__nv_bfloat162*)p_As2, (__nv_bfloat162*)p_Au2, last ? 0 : 1);
    }

    // outputs
    mean_kernel<<<rb, 256>>>((const float4*)p_hs, (const float4*)(p_hs + HN),
                             (const float4*)(p_hs + 2 * HN),
                             (const float4*)p_hu, (const float4*)(p_hu + HN),
                             (const float4*)(p_hu + 2 * HN),
                             (float4*)out, NHID / 4);
    out_head_kernel<<<(2 * N_SPOT * 32 + 255) / 256, 256>>>(
        p_hs + 2 * HN, p_hu + 2 * HN, W_out_s, b_out_s, W_out_u, b_out_u,
        out + 2 * (size_t)NHID, out + 2 * (size_t)NHID + N_SPOT);
}

// round 16
// speedup vs baseline: 1.1471x; 1.0651x over previous
#include <cuda_runtime.h>
#include <cuda_bf16.h>
#include <cstdint>

#define N_SPOT 30000
#define N_USER 30000
#define NE     600000
#define SPLIT  5
#define ATT_IN 512
#define HEADS  4
#define PER    128
#define HID    256
#define MPAD   30080   // 235 * 128

// ---------------- scratch (device globals; no allocation) ----------------
__device__ float g_wq[HEADS * ATT_IN];
__device__ float g_tmp_u[(size_t)N_USER * HID];
__device__ float g_tmp_s[(size_t)N_SPOT * HID];
__device__ float g_hs[3][(size_t)N_SPOT * HID];
__device__ float g_hu[3][(size_t)N_USER * HID];
__device__ float g_deg[4 * N_SPOT];
__device__ float g_rs[4 * N_SPOT];
__device__ int   g_off_us[N_SPOT + 1];
__device__ int   g_cur_us[N_SPOT];
__device__ int   g_csr_us[NE];
__device__ int   g_off_su[N_USER + 1];
__device__ int   g_cur_su[N_USER];
__device__ int   g_csr_su[NE];

// bf16 2-block split operands along K: [Ah | Al]  (row length = 2K)
__device__ __nv_bfloat16 g_A2att[(size_t)HEADS * MPAD * 1024];  // att: K=512
__device__ __nv_bfloat16 g_Au2[(size_t)MPAD * 1024];
__device__ __nv_bfloat16 g_As2[(size_t)MPAD * 1024];
// weights transposed [N][2K] as [Bh | Bl]
#define WOFF_ATT   0
#define WOFF_L0US  (4 * 128 * 1024)
#define WOFF_L0SU  (WOFF_L0US + 256 * 1024)
#define WOFF_MUS   (WOFF_L0SU + 256 * 1024)
#define WOFF_MSU   (WOFF_MUS + 2 * 256 * 512)
#define WTOT       (WOFF_MSU + 2 * 256 * 512)
__device__ __nv_bfloat16 g_B2[WTOT];

// ---------------- helpers ----------------
__device__ __forceinline__ uint32_t smem_u32(const void* p) {
    uint32_t r;
    asm("{ .reg .u64 t; cvta.to.shared.u64 t, %1; cvt.u32.u64 %0, t; }" : "=r"(r) : "l"(p));
    return r;
}
__device__ __forceinline__ void ldsm4(uint32_t addr, uint32_t& r0, uint32_t& r1,
                                      uint32_t& r2, uint32_t& r3) {
    asm volatile("ldmatrix.sync.aligned.m8n8.x4.shared.b16 {%0,%1,%2,%3}, [%4];"
                 : "=r"(r0), "=r"(r1), "=r"(r2), "=r"(r3) : "r"(addr));
}
__device__ __forceinline__ void mma16816(float* d, const uint32_t* a, const uint32_t* b) {
    asm volatile(
        "mma.sync.aligned.m16n8k16.row.col.f32.bf16.bf16.f32 "
        "{%0,%1,%2,%3}, {%4,%5,%6,%7}, {%8,%9}, {%0,%1,%2,%3};"
        : "+f"(d[0]), "+f"(d[1]), "+f"(d[2]), "+f"(d[3])
        : "r"(a[0]), "r"(a[1]), "r"(a[2]), "r"(a[3]), "r"(b[0]), "r"(b[1]));
}
#define CP16(dst, src) \
    asm volatile("cp.async.ca.shared.global [%0], [%1], 16;" :: "r"(dst), "l"(src))
#define CPCOMMIT() asm volatile("cp.async.commit_group;" ::: "memory")

// ---------------- degree / norm ----------------
__global__ void deg_count_kernel(const int* __restrict__ e_us, const int* __restrict__ e_su,
                                 float* __restrict__ deg) {
    int i = blockIdx.x * blockDim.x + threadIdx.x;
    if (i < NE) {
        atomicAdd(&deg[0 * N_SPOT + e_us[i]], 1.0f);
        atomicAdd(&deg[1 * N_SPOT + e_us[NE + i]], 1.0f);
        atomicAdd(&deg[2 * N_SPOT + e_su[i]], 1.0f);
        atomicAdd(&deg[3 * N_SPOT + e_su[NE + i]], 1.0f);
    }
}

__global__ void rsqrt_kernel(const float* __restrict__ deg, float* __restrict__ rs) {
    int i = blockIdx.x * blockDim.x + threadIdx.x;
    if (i < 4 * N_SPOT) {
        float d = deg[i];
        rs[i] = d > 0.f ? rsqrtf(d) : 0.f;
    }
}

// ---------------- CSR build ----------------
__global__ __launch_bounds__(1024) void scan2_kernel(const float* __restrict__ degall,
                                                     int* __restrict__ off_us, int* __restrict__ cur_us,
                                                     int* __restrict__ off_su, int* __restrict__ cur_su) {
    const float* deg = (blockIdx.x == 0) ? degall + 1 * N_SPOT : degall + 3 * N_SPOT;
    int* off = (blockIdx.x == 0) ? off_us : off_su;
    int* cur = (blockIdx.x == 0) ? cur_us : cur_su;
    const int n = N_SPOT;
    __shared__ int part[1024];
    const int t = threadIdx.x;
    const int CH = (n + 1023) / 1024;
    const int base = t * CH;
    int s = 0;
    for (int j = 0; j < CH; j++) {
        int idx = base + j;
        if (idx < n) s += (int)deg[idx];
    }
    part[t] = s;
    __syncthreads();
    for (int o = 1; o < 1024; o <<= 1) {
        int v = (t >= o) ? part[t - o] : 0;
        __syncthreads();
        part[t] += v;
        __syncthreads();
    }
    int run = t ? part[t - 1] : 0;
    for (int j = 0; j < CH; j++) {
        int idx = base + j;
        if (idx < n) {
            off[idx] = run;
            cur[idx] = run;
            run += (int)deg[idx];
        }
    }
    if (t == 0) off[n] = part[1023];
}

__global__ void fill_both_kernel(const int* __restrict__ e_us, const int* __restrict__ e_su,
                                 int* __restrict__ cur_us, int* __restrict__ csr_us,
                                 int* __restrict__ cur_su, int* __restrict__ csr_su) {
    int e = blockIdx.x * blockDim.x + threadIdx.x;
    if (e < NE) {
        int p = atomicAdd(&cur_us[e_us[NE + e]], 1);
        csr_us[p] = e_us[e];
        int q = atomicAdd(&cur_su[e_su[NE + e]], 1);
        csr_su[q] = e_su[e];
    }
}

// ---------------- all weight transposes+splits in one kernel ----------------
__device__ __forceinline__ void wsplit(const float* __restrict__ W, int K, int N,
                                       __nv_bfloat16* __restrict__ dst, int idx) {
    int n = idx / K, k = idx - n * K;
    float v = W[(size_t)k * N + n];
    __nv_bfloat16 h = __float2bfloat16(v);
    float r = v - __bfloat162float(h);
    size_t base = (size_t)n * 2 * K;
    dst[base + k] = h;
    dst[base + K + k] = __float2bfloat16(r);
}

__global__ void wprep_all_kernel(const float* __restrict__ W_att,
                                 const float* __restrict__ W0_us,
                                 const float* __restrict__ W0_su,
                                 const float* __restrict__ Wmid_us,
                                 const float* __restrict__ Wmid_su,
                                 __nv_bfloat16* __restrict__ B2) {
    long t = (long)blockIdx.x * 256 + threadIdx.x;
    const long E_ATT = 4L * 65536, E_L0 = 131072;
    if (t < E_ATT) {
        int h = (int)(t >> 16), r = (int)(t & 65535);
        wsplit(W_att + (size_t)h * 65536, 512, 128, B2 + WOFF_ATT + (size_t)h * 128 * 1024, r);
    } else if (t < E_ATT + E_L0) {
        wsplit(W0_us, 512, 256, B2 + WOFF_L0US, (int)(t - E_ATT));
    } else if (t < E_ATT + 2 * E_L0) {
        wsplit(W0_su, 512, 256, B2 + WOFF_L0SU, (int)(t - E_ATT - E_L0));
    } else {
        long u = t - E_ATT - 2 * E_L0;  // 4 x 65536: mus0, mus1, msu0, msu1
        int seg = (int)(u >> 16), r = (int)(u & 65535);
        int l = seg & 1;
        if (seg < 2)
            wsplit(Wmid_us + (size_t)l * 65536, 256, 256, B2 + WOFF_MUS + (size_t)l * 131072, r);
        else
            wsplit(Wmid_su + (size_t)l * 65536, 256, 256, B2 + WOFF_MSU + (size_t)l * 131072, r);
    }
}

// ---------------- fp32 -> A2[M][2K] = [Ah|Al] with row scale (layer-0 user) ------------
__global__ void aconv_kernel(const float4* __restrict__ in, const float* __restrict__ rs,
                             int M, int Kq, int Mpad,
                             __nv_bfloat162* __restrict__ out2) {
    int idx = blockIdx.x * 256 + threadIdx.x;
    if (idx >= Mpad * Kq) return;
    int row = idx / Kq, q = idx - row * Kq;
    const int K = Kq * 4;
    float4 v = make_float4(0.f, 0.f, 0.f, 0.f);
    if (row < M) {
        v = in[idx];
        float sc = rs[row];
        v.x *= sc; v.y *= sc; v.z *= sc; v.w *= sc;
    }
    __nv_bfloat16 hx = __float2bfloat16(v.x), hy = __float2bfloat16(v.y);
    __nv_bfloat16 hz = __float2bfloat16(v.z), hw = __float2bfloat16(v.w);
    float rx = v.x - __bfloat162float(hx), ry = v.y - __bfloat162float(hy);
    float rz = v.z - __bfloat162float(hz), rw = v.w - __bfloat162float(hw);
    size_t b2 = (size_t)row * K;  // bf162 units per row = K
    out2[b2 + 2 * q + 0] = __nv_bfloat162(hx, hy);
    out2[b2 + 2 * q + 1] = __nv_bfloat162(hz, hw);
    out2[b2 + K / 2 + 2 * q + 0] = __nv_bfloat162(__float2bfloat16(rx), __float2bfloat16(ry));
    out2[b2 + K / 2 + 2 * q + 1] = __nv_bfloat162(__float2bfloat16(rz), __float2bfloat16(rw));
}

// ---------------- attention ----------------
__global__ void wq_kernel(const float* __restrict__ W, const float* __restrict__ q,
                          float* __restrict__ wq) {
    int t = blockIdx.x * blockDim.x + threadIdx.x;
    if (t >= HEADS * ATT_IN) return;
    int h = t / ATT_IN, i = t % ATT_IN;
    const float* w = W + ((size_t)h * ATT_IN + i) * PER;
    const float* qq = q + h * PER;
    float s = 0.f;
#pragma unroll 8
    for (int p = 0; p < PER; p++) s += w[p] * qq[p];
    wq[t] = s;
}

__global__ __launch_bounds__(128) void att_kernel(const float* __restrict__ x,
                                                  const float* __restrict__ wq,
                                                  __nv_bfloat16* __restrict__ A2) {
    int n = blockIdx.x;
    __shared__ float sx[SPLIT * ATT_IN];
    __shared__ float satt[HEADS][SPLIT];
    const float4* xr4 = (const float4*)(x + (size_t)n * (SPLIT * ATT_IN));
#pragma unroll
    for (int j = 0; j < SPLIT; j++)
        ((float4*)sx)[threadIdx.x + 128 * j] = xr4[threadIdx.x + 128 * j];
    __syncthreads();

    int w = threadIdx.x >> 5, lane = threadIdx.x & 31;
    if (w < HEADS) {
        float lg[SPLIT];
#pragma unroll
        for (int s = 0; s < SPLIT; s++) {
            float p = 0.f;
            for (int i = lane; i < ATT_IN; i += 32) p += sx[s * ATT_IN + i] * wq[w * ATT_IN + i];
#pragma unroll
            for (int o = 16; o; o >>= 1) p += __shfl_down_sync(0xffffffffu, p, o);
            lg[s] = p;
        }
        if (lane == 0) {
            float mx = -1e30f;
#pragma unroll
            for (int s = 0; s < SPLIT; s++) {
                lg[s] = lg[s] >= 0.f ? lg[s] : 0.2f * lg[s];
                mx = fmaxf(mx, lg[s]);
            }
            float sum = 0.f;
#pragma unroll
            for (int s = 0; s < SPLIT; s++) { lg[s] = expf(lg[s] - mx); sum += lg[s]; }
            float r = 1.f / sum;
#pragma unroll
            for (int s = 0; s < SPLIT; s++) satt[w][s] = lg[s] * r;
        }
    }
    __syncthreads();

    const int i4 = threadIdx.x * 4;
#pragma unroll
    for (int h = 0; h < HEADS; h++) {
        float a0 = satt[h][0], a1 = satt[h][1], a2 = satt[h][2], a3 = satt[h][3], a4 = satt[h][4];
        float4 r0 = *(const float4*)&sx[0 * ATT_IN + i4];
        float4 r1 = *(const float4*)&sx[1 * ATT_IN + i4];
        float4 r2 = *(const float4*)&sx[2 * ATT_IN + i4];
        float4 r3 = *(const float4*)&sx[3 * ATT_IN + i4];
        float4 r4 = *(const float4*)&sx[4 * ATT_IN + i4];
        float y0 = a0 * r0.x + a1 * r1.x + a2 * r2.x + a3 * r3.x + a4 * r4.x;
        float y1 = a0 * r0.y + a1 * r1.y + a2 * r2.y + a3 * r3.y + a4 * r4.y;
        float y2 = a0 * r0.z + a1 * r1.z + a2 * r2.z + a3 * r3.z + a4 * r4.z;
        float y3 = a0 * r0.w + a1 * r1.w + a2 * r2.w + a3 * r3.w + a4 * r4.w;
        __nv_bfloat16 h0 = __float2bfloat16(y0), h1 = __float2bfloat16(y1);
        __nv_bfloat16 h2 = __float2bfloat16(y2), h3 = __float2bfloat16(y3);
        float l0 = y0 - __bfloat162float(h0), l1 = y1 - __bfloat162float(h1);
        float l2 = y2 - __bfloat162float(h2), l3 = y3 - __bfloat162float(h3);
        union { __nv_bfloat162 b[2]; uint2 u; } hv, lv;
        hv.b[0] = __nv_bfloat162(h0, h1); hv.b[1] = __nv_bfloat162(h2, h3);
        lv.b[0] = __nv_bfloat162(__float2bfloat16(l0), __float2bfloat16(l1));
        lv.b[1] = __nv_bfloat162(__float2bfloat16(l2), __float2bfloat16(l3));
        size_t base = ((size_t)h * MPAD + n) * 1024;
        *(uint2*)(A2 + base + i4) = hv.u;
        *(uint2*)(A2 + base + 512 + i4) = lv.u;
    }
}

// ---------------- bf16 HMMA GEMM, 2-stage cp.async pipeline, 3-product split ----------------
#define STG 2
template <int EPI>
__global__ __launch_bounds__(256, 2) void hmma_gemm(
    const __nv_bfloat16* __restrict__ A2, int lda,
    const __nv_bfloat16* __restrict__ B2, int ldb,
    float* __restrict__ C, __nv_bfloat162* __restrict__ outb,
    const float* __restrict__ rsp,
    int ldc, int M, int K,
    long sA, long sB, long sC) {
    extern __shared__ __align__(16) char smem[];
    uint32_t sb = smem_u32(smem);
    const int tid = threadIdx.x;
    const int wid = tid >> 5, lane = tid & 31;
    A2 += (long)blockIdx.z * sA;
    B2 += (long)blockIdx.z * sB;
    int col0 = 0;
    if (EPI == 0) C += (long)blockIdx.z * sC;
    else col0 = (int)((long)blockIdx.z * sC);
    const int m0 = blockIdx.x * 128;
    const int n0 = blockIdx.y * 128;
    const int wm = (wid & 3) * 32;
    const int wn = (wid >> 2) * 64;

    float acc[2][8][4];
#pragma unroll
    for (int i = 0; i < 2; i++)
#pragma unroll
        for (int j = 0; j < 8; j++)
#pragma unroll
            for (int v = 0; v < 4; v++) acc[i][j][v] = 0.f;

#define OFFS(ch, ka, kb)                                   \
    {                                                      \
        int bq = (ch) / 3, br_ = (ch) - 3 * bq;            \
        ka = bq * 64 + (br_ == 1 ? K : 0);                 \
        kb = bq * 64 + (br_ == 2 ? K : 0);                 \
    }

#define COPY(buf, ka, kb)                                                                 \
    {                                                                                     \
        _Pragma("unroll")                                                                 \
        for (int j = 0; j < 4; j++) {                                                     \
            int idx = tid + 256 * j;                                                      \
            int r = idx >> 3, c = idx & 7;                                                \
            uint32_t da = sb + (buf) * 36864 + r * 144 + c * 16;                          \
            CP16(da, A2 + (size_t)(m0 + r) * lda + (ka) + c * 8);                         \
            CP16(da + 18432, B2 + (size_t)(n0 + r) * ldb + (kb) + c * 8);                 \
        }                                                                                 \
        CPCOMMIT();                                                                       \
    }

#define COMPUTE(buf)                                                                      \
    {                                                                                     \
        uint32_t aBase = sb + (buf) * 36864;                                              \
        uint32_t bBase = aBase + 18432;                                                   \
        _Pragma("unroll")                                                                 \
        for (int ks = 0; ks < 4; ks++) {                                                  \
            uint32_t af[2][4], bf[4][4];                                                  \
            int kb_ = ks * 32;                                                            \
            _Pragma("unroll")                                                             \
            for (int i = 0; i < 2; i++) {                                                 \
                uint32_t row = wm + i * 16 + (lane & 15);                                 \
                uint32_t addr = aBase + row * 144 + kb_ + (lane >> 4) * 16;               \
                ldsm4(addr, af[i][0], af[i][1], af[i][2], af[i][3]);                      \
            }                                                                             \
            _Pragma("unroll")                                                             \
            for (int j = 0; j < 4; j++) {                                                 \
                uint32_t g = lane >> 3, r8 = lane & 7;                                    \
                uint32_t row = wn + j * 16 + ((g >> 1) & 1) * 8 + r8;                     \
                uint32_t addr = bBase + row * 144 + kb_ + (g & 1) * 16;                   \
                ldsm4(addr, bf[j][0], bf[j][1], bf[j][2], bf[j][3]);                      \
            }                                                                             \
            _Pragma("unroll")                                                             \
            for (int i = 0; i < 2; i++)                                                   \
                _Pragma("unroll")                                                         \
                for (int j = 0; j < 4; j++) {                                             \
                    mma16816(acc[i][2 * j], af[i], &bf[j][0]);                            \
                    mma16816(acc[i][2 * j + 1], af[i], &bf[j][2]);                        \
                }                                                                         \
        }                                                                                 \
    }

    const int nch = 3 * (K >> 6);
    {
        int ka, kb;
        OFFS(0, ka, kb);
        COPY(0, ka, kb);
    }
    for (int ch = 0; ch < nch; ch++) {
        if (ch + 1 < nch) {
            int ka, kb;
            OFFS(ch + 1, ka, kb);
            COPY((ch + 1) & 1, ka, kb);
            asm volatile("cp.async.wait_group 1;" ::: "memory");
        } else {
            asm volatile("cp.async.wait_group 0;" ::: "memory");
        }
        __syncthreads();
        COMPUTE(ch & 1);
        __syncthreads();
    }

#pragma unroll
    for (int i = 0; i < 2; i++) {
#pragma unroll
        for (int j = 0; j < 8; j++) {
            int mA = m0 + wm + i * 16 + (lane >> 2);
            int col = n0 + wn + j * 8 + 2 * (lane & 3);
            if (EPI == 0) {
                if (mA < M) {
                    float2 v = make_float2(acc[i][j][0], acc[i][j][1]);
                    *(float2*)(C + (size_t)mA * ldc + col) = v;
                }
                if (mA + 8 < M) {
                    float2 v = make_float2(acc[i][j][2], acc[i][j][3]);
                    *(float2*)(C + (size_t)(mA + 8) * ldc + col) = v;
                }
            } else {
#pragma unroll
                for (int hh = 0; hh < 2; hh++) {
                    int m = mA + 8 * hh;
                    if (m < M) {
                        float sc = rsp[m];
                        float v0 = acc[i][j][2 * hh] * sc;
                        float v1 = acc[i][j][2 * hh + 1] * sc;
                        __nv_bfloat16 h0 = __float2bfloat16(v0);
                        __nv_bfloat16 h1 = __float2bfloat16(v1);
                        float l0 = v0 - __bfloat162float(h0);
                        float l1 = v1 - __bfloat162float(h1);
                        size_t base = (size_t)m * ldc + col0 + col;
                        outb[base >> 1] = __nv_bfloat162(h0, h1);
                        outb[(base + (ldc >> 1)) >> 1] =
                            __nv_bfloat162(__float2bfloat16(l0), __float2bfloat16(l1));
                    }
                }
            }
        }
    }
#undef OFFS
#undef COPY
#undef COMPUTE
}

// ---------------- merged CSR gather (fp32 msgs, dst norm + next-layer emit) --------
__global__ __launch_bounds__(256) void gather_both_kernel(
    const float4* __restrict__ msg_u, const float4* __restrict__ msg_s,
    const int* __restrict__ off_us, const int* __restrict__ csr_us,
    const int* __restrict__ off_su, const int* __restrict__ csr_su,
    const float* __restrict__ rs,
    float4* __restrict__ out_s, float4* __restrict__ out_u,
    __nv_bfloat162* __restrict__ a2_s, __nv_bfloat162* __restrict__ a2_u, int emit) {
    int g = blockIdx.x * 4 + (threadIdx.x >> 6);
    int c = threadIdx.x & 63;
    const float4* msg;
    const int *off, *csr;
    const float *rd, *rsn;
    float4* out;
    __nv_bfloat162* a2;
    int node;
    if (g < N_SPOT) {
        node = g;
        msg = msg_u; off = off_us; csr = csr_us;
        rd = rs + 1 * N_SPOT; rsn = rs + 2 * N_SPOT;
        out = out_s; a2 = a2_s;
    } else {
        node = g - N_SPOT;
        if (node >= N_USER) return;
        msg = msg_s; off = off_su; csr = csr_su;
        rd = rs + 3 * N_SPOT; rsn = rs + 0 * N_SPOT;
        out = out_u; a2 = a2_u;
    }
    int b = off[node], e = off[node + 1];
    float4 acc = make_float4(0.f, 0.f, 0.f, 0.f);
#define ACCUM(sid)                                                       \
    {                                                                    \
        float4 v = __ldg(&msg[(size_t)(sid) * 64 + c]);                  \
        acc.x += v.x; acc.y += v.y; acc.z += v.z; acc.w += v.w;          \
    }
    int i = b;
    for (; i + 8 <= e; i += 8) {
        int s0 = __ldg(&csr[i]), s1 = __ldg(&csr[i + 1]);
        int s2 = __ldg(&csr[i + 2]), s3 = __ldg(&csr[i + 3]);
        int s4 = __ldg(&csr[i + 4]), s5 = __ldg(&csr[i + 5]);
        int s6 = __ldg(&csr[i + 6]), s7 = __ldg(&csr[i + 7]);
        ACCUM(s0) ACCUM(s1) ACCUM(s2) ACCUM(s3)
        ACCUM(s4) ACCUM(s5) ACCUM(s6) ACCUM(s7)
    }
    for (; i < e; i++) {
        int s0 = __ldg(&csr[i]);
        ACCUM(s0)
    }
#undef ACCUM
    float sc = rd[node];
    acc.x *= sc; acc.y *= sc; acc.z *= sc; acc.w *= sc;
    out[(size_t)node * 64 + c] = acc;

    if (emit) {
        float s2c = rsn[node];
        float vx = fmaxf(acc.x, 0.f) * s2c, vy = fmaxf(acc.y, 0.f) * s2c;
        float vz = fmaxf(acc.z, 0.f) * s2c, vw = fmaxf(acc.w, 0.f) * s2c;
        __nv_bfloat16 hx = __float2bfloat16(vx), hy = __float2bfloat16(vy);
        __nv_bfloat16 hz = __float2bfloat16(vz), hw = __float2bfloat16(vw);
        float rx = vx - __bfloat162float(hx), ry = vy - __bfloat162float(hy);
        float rz = vz - __bfloat162float(hz), rw = vw - __bfloat162float(hw);
        size_t bb = (size_t)node * 256 + 2 * c;
        a2[bb + 0] = __nv_bfloat162(hx, hy);
        a2[bb + 1] = __nv_bfloat162(hz, hw);
        a2[bb + 128 + 0] = __nv_bfloat162(__float2bfloat16(rx), __float2bfloat16(ry));
        a2[bb + 128 + 1] = __nv_bfloat162(__float2bfloat16(rz), __float2bfloat16(rw));
    }
}

// ---------------- outputs ----------------
__global__ void mean_kernel(const float4* __restrict__ s0, const float4* __restrict__ s1,
                            const float4* __restrict__ s2,
                            const float4* __restrict__ u0, const float4* __restrict__ u1,
                            const float4* __restrict__ u2,
                            float4* __restrict__ out, int n4) {
    int i = blockIdx.x * blockDim.x + threadIdx.x;
    if (i < n4) {
        const float r = 1.f / 3.f;
        float4 a = s0[i], b = s1[i], c = s2[i];
        float4 o;
        o.x = (fmaxf(a.x, 0.f) + fmaxf(b.x, 0.f) + fmaxf(c.x, 0.f)) * r;
        o.y = (fmaxf(a.y, 0.f) + fmaxf(b.y, 0.f) + fmaxf(c.y, 0.f)) * r;
        o.z = (fmaxf(a.z, 0.f) + fmaxf(b.z, 0.f) + fmaxf(c.z, 0.f)) * r;
        o.w = (fmaxf(a.w, 0.f) + fmaxf(b.w, 0.f) + fmaxf(c.w, 0.f)) * r;
        out[i] = o;
        a = u0[i]; b = u1[i]; c = u2[i];
        o.x = (fmaxf(a.x, 0.f) + fmaxf(b.x, 0.f) + fmaxf(c.x, 0.f)) * r;
        o.y = (fmaxf(a.y, 0.f) + fmaxf(b.y, 0.f) + fmaxf(c.y, 0.f)) * r;
        o.z = (fmaxf(a.z, 0.f) + fmaxf(b.z, 0.f) + fmaxf(c.z, 0.f)) * r;
        o.w = (fmaxf(a.w, 0.f) + fmaxf(b.w, 0.f) + fmaxf(c.w, 0.f)) * r;
        out[n4 + i] = o;
    }
}

__global__ void out_head_kernel(const float* __restrict__ hs, const float* __restrict__ hu,
                                const float* __restrict__ Ws, const float* __restrict__ bs,
                                const float* __restrict__ Wu, const float* __restrict__ bu,
                                float* __restrict__ out_s, float* __restrict__ out_u) {
    int warp = (blockIdx.x * blockDim.x + threadIdx.x) >> 5;
    int lane = threadIdx.x & 31;
    if (warp < N_SPOT) {
        const float* x = hs + (size_t)warp * HID;
        float s = 0.f;
#pragma unroll
        for (int i = lane; i < HID; i += 32) s += fmaxf(x[i], 0.f) * Ws[i];
#pragma unroll
        for (int o = 16; o; o >>= 1) s += __shfl_down_sync(0xffffffffu, s, o);
        if (lane == 0) out_s[warp] = s + bs[0];
    } else if (warp < 2 * N_SPOT) {
        int n = warp - N_SPOT;
        const float* x = hu + (size_t)n * HID;
        float s = 0.f;
#pragma unroll
        for (int i = lane; i < HID; i += 32) s += fmaxf(x[i], 0.f) * Wu[i];
#pragma unroll
        for (int o = 16; o; o >>= 1) s += __shfl_down_sync(0xffffffffu, s, o);
        if (lane == 0) out_u[n] = s + bu[0];
    }
}

// ---------------- host ----------------
static float* sym_addr(const void* sym) {
    void* p = nullptr;
    cudaGetSymbolAddress(&p, sym);
    return (float*)p;
}
static int* sym_addr_i(const void* sym) {
    void* p = nullptr;
    cudaGetSymbolAddress(&p, sym);
    return (int*)p;
}
static __nv_bfloat16* sym_addr_b(const void* sym) {
    void* p = nullptr;
    cudaGetSymbolAddress(&p, sym);
    return (__nv_bfloat16*)p;
}

extern "C" void kernel_launch(void* const* d_in, const int* in_sizes, int n_in,
                              void* d_out, int out_size) {
    const float* x_spot  = (const float*)d_in[0];
    const float* x_user  = (const float*)d_in[1];
    const int*   edge_us = (const int*)d_in[2];
    const int*   edge_su = (const int*)d_in[3];
    const float* W_att   = (const float*)d_in[4];
    const float* q_att   = (const float*)d_in[5];
    const float* W0_us   = (const float*)d_in[6];
    const float* W0_su   = (const float*)d_in[7];
    const float* Wmid_us = (const float*)d_in[8];
    const float* Wmid_su = (const float*)d_in[9];
    const float* W_out_s = (const float*)d_in[10];
    const float* b_out_s = (const float*)d_in[11];
    const float* W_out_u = (const float*)d_in[12];
    const float* b_out_u = (const float*)d_in[13];
    float* out = (float*)d_out;

    float* p_wq    = sym_addr(g_wq);
    float* p_tmp_u = sym_addr(g_tmp_u);
    float* p_tmp_s = sym_addr(g_tmp_s);
    float* p_hs    = sym_addr(g_hs);
    float* p_hu    = sym_addr(g_hu);
    float* p_deg   = sym_addr(g_deg);
    float* p_rs    = sym_addr(g_rs);
    int* p_off_us  = sym_addr_i(g_off_us);
    int* p_cur_us  = sym_addr_i(g_cur_us);
    int* p_csr_us  = sym_addr_i(g_csr_us);
    int* p_off_su  = sym_addr_i(g_off_su);
    int* p_cur_su  = sym_addr_i(g_cur_su);
    int* p_csr_su  = sym_addr_i(g_csr_su);
    __nv_bfloat16* p_A2att = sym_addr_b(g_A2att);
    __nv_bfloat16* p_Au2   = sym_addr_b(g_Au2);
    __nv_bfloat16* p_As2   = sym_addr_b(g_As2);
    __nv_bfloat16* p_B2    = sym_addr_b(g_B2);

    // side streams + fork/join events (created once; host objects only)
    static cudaStream_t s1 = nullptr, s2 = nullptr;
    static cudaEvent_t e0 = nullptr, eRS = nullptr, eAU = nullptr, eCSR = nullptr;
    if (!s1) {
        cudaStreamCreateWithFlags(&s1, cudaStreamNonBlocking);
        cudaStreamCreateWithFlags(&s2, cudaStreamNonBlocking);
        cudaEventCreateWithFlags(&e0, cudaEventDisableTiming);
        cudaEventCreateWithFlags(&eRS, cudaEventDisableTiming);
        cudaEventCreateWithFlags(&eAU, cudaEventDisableTiming);
        cudaEventCreateWithFlags(&eCSR, cudaEventDisableTiming);
    }

    const size_t HN = (size_t)N_SPOT * HID;
    const int NHID = N_SPOT * HID;
    const int SMEM = STG * 36864;  // 73728
    cudaFuncSetAttribute(hmma_gemm<0>, cudaFuncAttributeMaxDynamicSharedMemorySize, SMEM);
    cudaFuncSetAttribute(hmma_gemm<1>, cudaFuncAttributeMaxDynamicSharedMemorySize, SMEM);

    const long sA_us = (long)(p_As2 - p_Au2);
    const long sC_us = (long)(p_tmp_s - p_tmp_u);
    int eb = (NE + 255) / 256;
    int gb2 = (2 * N_SPOT + 3) / 4;
    int rb = (NHID / 4 + 255) / 256;

    // ---- fork: prep chain on s1, aconv on s2 ----
    cudaEventRecord(e0, 0);
    cudaStreamWaitEvent(s1, e0, 0);
    cudaStreamWaitEvent(s2, e0, 0);

    // s1: deg -> rs -> CSR
    cudaMemsetAsync(p_deg, 0, 4 * N_SPOT * sizeof(float), s1);
    deg_count_kernel<<<eb, 256, 0, s1>>>(edge_us, edge_su, p_deg);
    rsqrt_kernel<<<(4 * N_SPOT + 255) / 256, 256, 0, s1>>>(p_deg, p_rs);
    cudaEventRecord(eRS, s1);
    scan2_kernel<<<2, 1024, 0, s1>>>(p_deg, p_off_us, p_cur_us, p_off_su, p_cur_su);
    fill_both_kernel<<<eb, 256, 0, s1>>>(edge_us, edge_su, p_cur_us, p_csr_us,
                                         p_cur_su, p_csr_su);
    cudaEventRecord(eCSR, s1);

    // s2: layer-0 user A operand (needs rs)
    cudaStreamWaitEvent(s2, eRS, 0);
    aconv_kernel<<<(MPAD * 128 + 255) / 256, 256, 0, s2>>>(
        (const float4*)x_user, p_rs + 0 * N_SPOT, N_USER, 128, MPAD,
        (__nv_bfloat162*)p_Au2);
    cudaEventRecord(eAU, s2);

    // ---- origin stream: attention pipeline ----
    wq_kernel<<<(HEADS * ATT_IN + 255) / 256, 256>>>(W_att, q_att, p_wq);
    wprep_all_kernel<<<3072, 256>>>(W_att, W0_us, W0_su, Wmid_us, Wmid_su, p_B2);
    att_kernel<<<N_SPOT, 128>>>(x_spot, p_wq, p_A2att);
    cudaStreamWaitEvent(0, eRS, 0);
    // attention GEMM — writes layer-0 spot A operand (scaled by spot src norm)
    hmma_gemm<1><<<dim3(MPAD / 128, 1, HEADS), 256, SMEM>>>(
        p_A2att, 1024, p_B2 + WOFF_ATT, 1024, nullptr,
        (__nv_bfloat162*)p_As2, p_rs + 2 * N_SPOT,
        1024, N_SPOT, 512,
        (long)MPAD * 1024, (long)128 * 1024, 128);
    cudaStreamWaitEvent(0, eAU, 0);
    // layer-0 GEMMs merged (z=0 user, z=1 spot)
    hmma_gemm<0><<<dim3(MPAD / 128, 2, 2), 256, SMEM>>>(
        p_Au2, 1024, p_B2 + WOFF_L0US, 1024, p_tmp_u, nullptr, nullptr,
        HID, N_SPOT, 512, sA_us, (long)(WOFF_L0SU - WOFF_L0US), sC_us);
    cudaStreamWaitEvent(0, eCSR, 0);
    // gathers merged (dst norm; emit next-layer A operands with src norm)
    gather_both_kernel<<<gb2, 256>>>(
        (const float4*)p_tmp_u, (const float4*)p_tmp_s,
        p_off_us, p_csr_us, p_off_su, p_csr_su, p_rs,
        (float4*)p_hs, (float4*)p_hu,
        (__nv_bfloat162*)p_As2, (__nv_bfloat162*)p_Au2, 1);

    // mid layers
    for (int l = 1; l < 3; l++) {
        float* hs_new = p_hs + l * HN;
        float* hu_new = p_hu + l * HN;
        bool last = (l == 2);
        hmma_gemm<0><<<dim3(MPAD / 128, 2, 2), 256, SMEM>>>(
            p_Au2, 512, p_B2 + WOFF_MUS + (l - 1) * 131072, 512, p_tmp_u, nullptr, nullptr,
            HID, N_SPOT, 256, sA_us, (long)(WOFF_MSU - WOFF_MUS), sC_us);
        gather_both_kernel<<<gb2, 256>>>(
            (const float4*)p_tmp_u, (const float4*)p_tmp_s,
            p_off_us, p_csr_us, p_off_su, p_csr_su, p_rs,
            (float4*)hs_new, (float4*)hu_new,
            (__nv_bfloat162*)p_As2, (__nv_bfloat162*)p_Au2, last ? 0 : 1);
    }

    // outputs
    mean_kernel<<<rb, 256>>>((const float4*)p_hs, (const float4*)(p_hs + HN),
                             (const float4*)(p_hs + 2 * HN),
                             (const float4*)p_hu, (const float4*)(p_hu + HN),
                             (const float4*)(p_hu + 2 * HN),
                             (float4*)out, NHID / 4);
    out_head_kernel<<<(2 * N_SPOT * 32 + 255) / 256, 256>>>(
        p_hs + 2 * HN, p_hu + 2 * HN, W_out_s, b_out_s, W_out_u, b_out_u,
        out + 2 * (size_t)NHID, out + 2 * (size_t)NHID + N_SPOT);
}

// round 17
// speedup vs baseline: 1.2582x; 1.0968x over previous
#include <cuda_runtime.h>
#include <cuda_bf16.h>
#include <cstdint>

#define N_SPOT 30000
#define N_USER 30000
#define NE     600000
#define SPLIT  5
#define ATT_IN 512
#define HEADS  4
#define PER    128
#define HID    256
#define MPAD   30080   // 235 * 128

// ---------------- scratch (device globals; no allocation) ----------------
__device__ float g_wq[HEADS * ATT_IN];
__device__ float g_tmp_u[(size_t)N_USER * HID];
__device__ float g_tmp_s[(size_t)N_SPOT * HID];
__device__ float g_hs[3][(size_t)N_SPOT * HID];
__device__ float g_hu[3][(size_t)N_USER * HID];
__device__ float g_deg[4 * N_SPOT];
__device__ float g_rs[4 * N_SPOT];
__device__ int   g_off_us[N_SPOT + 1];
__device__ int   g_cur_us[N_SPOT];
__device__ int   g_csr_us[NE];
__device__ int   g_off_su[N_USER + 1];
__device__ int   g_cur_su[N_USER];
__device__ int   g_csr_su[NE];

// bf16 2-block split operands [Ah | Al]; ping-pong buffers for chain overlap
__device__ __nv_bfloat16 g_A2att[(size_t)HEADS * MPAD * 1024];  // att: K=512
__device__ __nv_bfloat16 g_Au2[2][(size_t)MPAD * 1024];
__device__ __nv_bfloat16 g_As2[2][(size_t)MPAD * 1024];
// weights transposed [N][2K] as [Bh | Bl]
#define WOFF_ATT   0
#define WOFF_L0US  (4 * 128 * 1024)
#define WOFF_L0SU  (WOFF_L0US + 256 * 1024)
#define WOFF_MUS   (WOFF_L0SU + 256 * 1024)
#define WOFF_MSU   (WOFF_MUS + 2 * 256 * 512)
#define WTOT       (WOFF_MSU + 2 * 256 * 512)
__device__ __nv_bfloat16 g_B2[WTOT];

// ---------------- helpers ----------------
__device__ __forceinline__ uint32_t smem_u32(const void* p) {
    uint32_t r;
    asm("{ .reg .u64 t; cvta.to.shared.u64 t, %1; cvt.u32.u64 %0, t; }" : "=r"(r) : "l"(p));
    return r;
}
__device__ __forceinline__ void ldsm4(uint32_t addr, uint32_t& r0, uint32_t& r1,
                                      uint32_t& r2, uint32_t& r3) {
    asm volatile("ldmatrix.sync.aligned.m8n8.x4.shared.b16 {%0,%1,%2,%3}, [%4];"
                 : "=r"(r0), "=r"(r1), "=r"(r2), "=r"(r3) : "r"(addr));
}
__device__ __forceinline__ void mma16816(float* d, const uint32_t* a, const uint32_t* b) {
    asm volatile(
        "mma.sync.aligned.m16n8k16.row.col.f32.bf16.bf16.f32 "
        "{%0,%1,%2,%3}, {%4,%5,%6,%7}, {%8,%9}, {%0,%1,%2,%3};"
        : "+f"(d[0]), "+f"(d[1]), "+f"(d[2]), "+f"(d[3])
        : "r"(a[0]), "r"(a[1]), "r"(a[2]), "r"(a[3]), "r"(b[0]), "r"(b[1]));
}
#define CP16(dst, src) \
    asm volatile("cp.async.ca.shared.global [%0], [%1], 16;" :: "r"(dst), "l"(src))
#define CPCOMMIT() asm volatile("cp.async.commit_group;" ::: "memory")

// ---------------- degree / norm ----------------
__global__ void deg_count_kernel(const int* __restrict__ e_us, const int* __restrict__ e_su,
                                 float* __restrict__ deg) {
    int i = blockIdx.x * blockDim.x + threadIdx.x;
    if (i < NE) {
        atomicAdd(&deg[0 * N_SPOT + e_us[i]], 1.0f);
        atomicAdd(&deg[1 * N_SPOT + e_us[NE + i]], 1.0f);
        atomicAdd(&deg[2 * N_SPOT + e_su[i]], 1.0f);
        atomicAdd(&deg[3 * N_SPOT + e_su[NE + i]], 1.0f);
    }
}

__global__ void rsqrt_kernel(const float* __restrict__ deg, float* __restrict__ rs) {
    int i = blockIdx.x * blockDim.x + threadIdx.x;
    if (i < 4 * N_SPOT) {
        float d = deg[i];
        rs[i] = d > 0.f ? rsqrtf(d) : 0.f;
    }
}

// ---------------- CSR build ----------------
__global__ __launch_bounds__(1024) void scan2_kernel(const float* __restrict__ degall,
                                                     int* __restrict__ off_us, int* __restrict__ cur_us,
                                                     int* __restrict__ off_su, int* __restrict__ cur_su) {
    const float* deg = (blockIdx.x == 0) ? degall + 1 * N_SPOT : degall + 3 * N_SPOT;
    int* off = (blockIdx.x == 0) ? off_us : off_su;
    int* cur = (blockIdx.x == 0) ? cur_us : cur_su;
    const int n = N_SPOT;
    __shared__ int part[1024];
    const int t = threadIdx.x;
    const int CH = (n + 1023) / 1024;
    const int base = t * CH;
    int s = 0;
    for (int j = 0; j < CH; j++) {
        int idx = base + j;
        if (idx < n) s += (int)deg[idx];
    }
    part[t] = s;
    __syncthreads();
    for (int o = 1; o < 1024; o <<= 1) {
        int v = (t >= o) ? part[t - o] : 0;
        __syncthreads();
        part[t] += v;
        __syncthreads();
    }
    int run = t ? part[t - 1] : 0;
    for (int j = 0; j < CH; j++) {
        int idx = base + j;
        if (idx < n) {
            off[idx] = run;
            cur[idx] = run;
            run += (int)deg[idx];
        }
    }
    if (t == 0) off[n] = part[1023];
}

__global__ void fill_both_kernel(const int* __restrict__ e_us, const int* __restrict__ e_su,
                                 int* __restrict__ cur_us, int* __restrict__ csr_us,
                                 int* __restrict__ cur_su, int* __restrict__ csr_su) {
    int e = blockIdx.x * blockDim.x + threadIdx.x;
    if (e < NE) {
        int p = atomicAdd(&cur_us[e_us[NE + e]], 1);
        csr_us[p] = e_us[e];
        int q = atomicAdd(&cur_su[e_su[NE + e]], 1);
        csr_su[q] = e_su[e];
    }
}

// ---------------- all weight transposes+splits in one kernel ----------------
__device__ __forceinline__ void wsplit(const float* __restrict__ W, int K, int N,
                                       __nv_bfloat16* __restrict__ dst, int idx) {
    int n = idx / K, k = idx - n * K;
    float v = W[(size_t)k * N + n];
    __nv_bfloat16 h = __float2bfloat16(v);
    float r = v - __bfloat162float(h);
    size_t base = (size_t)n * 2 * K;
    dst[base + k] = h;
    dst[base + K + k] = __float2bfloat16(r);
}

__global__ void wprep_all_kernel(const float* __restrict__ W_att,
                                 const float* __restrict__ W0_us,
                                 const float* __restrict__ W0_su,
                                 const float* __restrict__ Wmid_us,
                                 const float* __restrict__ Wmid_su,
                                 __nv_bfloat16* __restrict__ B2) {
    long t = (long)blockIdx.x * 256 + threadIdx.x;
    const long E_ATT = 4L * 65536, E_L0 = 131072;
    if (t < E_ATT) {
        int h = (int)(t >> 16), r = (int)(t & 65535);
        wsplit(W_att + (size_t)h * 65536, 512, 128, B2 + WOFF_ATT + (size_t)h * 128 * 1024, r);
    } else if (t < E_ATT + E_L0) {
        wsplit(W0_us, 512, 256, B2 + WOFF_L0US, (int)(t - E_ATT));
    } else if (t < E_ATT + 2 * E_L0) {
        wsplit(W0_su, 512, 256, B2 + WOFF_L0SU, (int)(t - E_ATT - E_L0));
    } else {
        long u = t - E_ATT - 2 * E_L0;
        int seg = (int)(u >> 16), r = (int)(u & 65535);
        int l = seg & 1;
        if (seg < 2)
            wsplit(Wmid_us + (size_t)l * 65536, 256, 256, B2 + WOFF_MUS + (size_t)l * 131072, r);
        else
            wsplit(Wmid_su + (size_t)l * 65536, 256, 256, B2 + WOFF_MSU + (size_t)l * 131072, r);
    }
}

// ---------------- fp32 -> A2[M][2K] = [Ah|Al] with row scale (layer-0 user) ------------
__global__ void aconv_kernel(const float4* __restrict__ in, const float* __restrict__ rs,
                             int M, int Kq, int Mpad,
                             __nv_bfloat162* __restrict__ out2) {
    int idx = blockIdx.x * 256 + threadIdx.x;
    if (idx >= Mpad * Kq) return;
    int row = idx / Kq, q = idx - row * Kq;
    const int K = Kq * 4;
    float4 v = make_float4(0.f, 0.f, 0.f, 0.f);
    if (row < M) {
        v = in[idx];
        float sc = rs[row];
        v.x *= sc; v.y *= sc; v.z *= sc; v.w *= sc;
    }
    __nv_bfloat16 hx = __float2bfloat16(v.x), hy = __float2bfloat16(v.y);
    __nv_bfloat16 hz = __float2bfloat16(v.z), hw = __float2bfloat16(v.w);
    float rx = v.x - __bfloat162float(hx), ry = v.y - __bfloat162float(hy);
    float rz = v.z - __bfloat162float(hz), rw = v.w - __bfloat162float(hw);
    size_t b2 = (size_t)row * K;
    out2[b2 + 2 * q + 0] = __nv_bfloat162(hx, hy);
    out2[b2 + 2 * q + 1] = __nv_bfloat162(hz, hw);
    out2[b2 + K / 2 + 2 * q + 0] = __nv_bfloat162(__float2bfloat16(rx), __float2bfloat16(ry));
    out2[b2 + K / 2 + 2 * q + 1] = __nv_bfloat162(__float2bfloat16(rz), __float2bfloat16(rw));
}

// ---------------- attention ----------------
__global__ void wq_kernel(const float* __restrict__ W, const float* __restrict__ q,
                          float* __restrict__ wq) {
    int t = blockIdx.x * blockDim.x + threadIdx.x;
    if (t >= HEADS * ATT_IN) return;
    int h = t / ATT_IN, i = t % ATT_IN;
    const float* w = W + ((size_t)h * ATT_IN + i) * PER;
    const float* qq = q + h * PER;
    float s = 0.f;
#pragma unroll 8
    for (int p = 0; p < PER; p++) s += w[p] * qq[p];
    wq[t] = s;
}

__global__ __launch_bounds__(128) void att_kernel(const float* __restrict__ x,
                                                  const float* __restrict__ wq,
                                                  __nv_bfloat16* __restrict__ A2) {
    int n = blockIdx.x;
    __shared__ float sx[SPLIT * ATT_IN];
    __shared__ float satt[HEADS][SPLIT];
    const float4* xr4 = (const float4*)(x + (size_t)n * (SPLIT * ATT_IN));
#pragma unroll
    for (int j = 0; j < SPLIT; j++)
        ((float4*)sx)[threadIdx.x + 128 * j] = xr4[threadIdx.x + 128 * j];
    __syncthreads();

    int w = threadIdx.x >> 5, lane = threadIdx.x & 31;
    if (w < HEADS) {
        float lg[SPLIT];
#pragma unroll
        for (int s = 0; s < SPLIT; s++) {
            float p = 0.f;
            for (int i = lane; i < ATT_IN; i += 32) p += sx[s * ATT_IN + i] * wq[w * ATT_IN + i];
#pragma unroll
            for (int o = 16; o; o >>= 1) p += __shfl_down_sync(0xffffffffu, p, o);
            lg[s] = p;
        }
        if (lane == 0) {
            float mx = -1e30f;
#pragma unroll
            for (int s = 0; s < SPLIT; s++) {
                lg[s] = lg[s] >= 0.f ? lg[s] : 0.2f * lg[s];
                mx = fmaxf(mx, lg[s]);
            }
            float sum = 0.f;
#pragma unroll
            for (int s = 0; s < SPLIT; s++) { lg[s] = expf(lg[s] - mx); sum += lg[s]; }
            float r = 1.f / sum;
#pragma unroll
            for (int s = 0; s < SPLIT; s++) satt[w][s] = lg[s] * r;
        }
    }
    __syncthreads();

    const int i4 = threadIdx.x * 4;
#pragma unroll
    for (int h = 0; h < HEADS; h++) {
        float a0 = satt[h][0], a1 = satt[h][1], a2 = satt[h][2], a3 = satt[h][3], a4 = satt[h][4];
        float4 r0 = *(const float4*)&sx[0 * ATT_IN + i4];
        float4 r1 = *(const float4*)&sx[1 * ATT_IN + i4];
        float4 r2 = *(const float4*)&sx[2 * ATT_IN + i4];
        float4 r3 = *(const float4*)&sx[3 * ATT_IN + i4];
        float4 r4 = *(const float4*)&sx[4 * ATT_IN + i4];
        float y0 = a0 * r0.x + a1 * r1.x + a2 * r2.x + a3 * r3.x + a4 * r4.x;
        float y1 = a0 * r0.y + a1 * r1.y + a2 * r2.y + a3 * r3.y + a4 * r4.y;
        float y2 = a0 * r0.z + a1 * r1.z + a2 * r2.z + a3 * r3.z + a4 * r4.z;
        float y3 = a0 * r0.w + a1 * r1.w + a2 * r2.w + a3 * r3.w + a4 * r4.w;
        __nv_bfloat16 h0 = __float2bfloat16(y0), h1 = __float2bfloat16(y1);
        __nv_bfloat16 h2 = __float2bfloat16(y2), h3 = __float2bfloat16(y3);
        float l0 = y0 - __bfloat162float(h0), l1 = y1 - __bfloat162float(h1);
        float l2 = y2 - __bfloat162float(h2), l3 = y3 - __bfloat162float(h3);
        union { __nv_bfloat162 b[2]; uint2 u; } hv, lv;
        hv.b[0] = __nv_bfloat162(h0, h1); hv.b[1] = __nv_bfloat162(h2, h3);
        lv.b[0] = __nv_bfloat162(__float2bfloat16(l0), __float2bfloat16(l1));
        lv.b[1] = __nv_bfloat162(__float2bfloat16(l2), __float2bfloat16(l3));
        size_t base = ((size_t)h * MPAD + n) * 1024;
        *(uint2*)(A2 + base + i4) = hv.u;
        *(uint2*)(A2 + base + 512 + i4) = lv.u;
    }
}

// ---------------- bf16 HMMA GEMM, 2-stage cp.async pipeline, 3-product split ----------------
#define STG 2
template <int EPI>
__global__ __launch_bounds__(256, 2) void hmma_gemm(
    const __nv_bfloat16* __restrict__ A2, int lda,
    const __nv_bfloat16* __restrict__ B2, int ldb,
    float* __restrict__ C, __nv_bfloat162* __restrict__ outb,
    const float* __restrict__ rsp,
    int ldc, int M, int K,
    long sA, long sB, long sC) {
    extern __shared__ __align__(16) char smem[];
    uint32_t sb = smem_u32(smem);
    const int tid = threadIdx.x;
    const int wid = tid >> 5, lane = tid & 31;
    A2 += (long)blockIdx.z * sA;
    B2 += (long)blockIdx.z * sB;
    int col0 = 0;
    if (EPI == 0) C += (long)blockIdx.z * sC;
    else col0 = (int)((long)blockIdx.z * sC);
    const int m0 = blockIdx.x * 128;
    const int n0 = blockIdx.y * 128;
    const int wm = (wid & 3) * 32;
    const int wn = (wid >> 2) * 64;

    float acc[2][8][4];
#pragma unroll
    for (int i = 0; i < 2; i++)
#pragma unroll
        for (int j = 0; j < 8; j++)
#pragma unroll
            for (int v = 0; v < 4; v++) acc[i][j][v] = 0.f;

#define OFFS(ch, ka, kb)                                   \
    {                                                      \
        int bq = (ch) / 3, br_ = (ch) - 3 * bq;            \
        ka = bq * 64 + (br_ == 1 ? K : 0);                 \
        kb = bq * 64 + (br_ == 2 ? K : 0);                 \
    }

#define COPY(buf, ka, kb)                                                                 \
    {                                                                                     \
        _Pragma("unroll")                                                                 \
        for (int j = 0; j < 4; j++) {                                                     \
            int idx = tid + 256 * j;                                                      \
            int r = idx >> 3, c = idx & 7;                                                \
            uint32_t da = sb + (buf) * 36864 + r * 144 + c * 16;                          \
            CP16(da, A2 + (size_t)(m0 + r) * lda + (ka) + c * 8);                         \
            CP16(da + 18432, B2 + (size_t)(n0 + r) * ldb + (kb) + c * 8);                 \
        }                                                                                 \
        CPCOMMIT();                                                                       \
    }

#define COMPUTE(buf)                                                                      \
    {                                                                                     \
        uint32_t aBase = sb + (buf) * 36864;                                              \
        uint32_t bBase = aBase + 18432;                                                   \
        _Pragma("unroll")                                                                 \
        for (int ks = 0; ks < 4; ks++) {                                                  \
            uint32_t af[2][4], bf[4][4];                                                  \
            int kb_ = ks * 32;                                                            \
            _Pragma("unroll")                                                             \
            for (int i = 0; i < 2; i++) {                                                 \
                uint32_t row = wm + i * 16 + (lane & 15);                                 \
                uint32_t addr = aBase + row * 144 + kb_ + (lane >> 4) * 16;               \
                ldsm4(addr, af[i][0], af[i][1], af[i][2], af[i][3]);                      \
            }                                                                             \
            _Pragma("unroll")                                                             \
            for (int j = 0; j < 4; j++) {                                                 \
                uint32_t g = lane >> 3, r8 = lane & 7;                                    \
                uint32_t row = wn + j * 16 + ((g >> 1) & 1) * 8 + r8;                     \
                uint32_t addr = bBase + row * 144 + kb_ + (g & 1) * 16;                   \
                ldsm4(addr, bf[j][0], bf[j][1], bf[j][2], bf[j][3]);                      \
            }                                                                             \
            _Pragma("unroll")                                                             \
            for (int i = 0; i < 2; i++)                                                   \
                _Pragma("unroll")                                                         \
                for (int j = 0; j < 4; j++) {                                             \
                    mma16816(acc[i][2 * j], af[i], &bf[j][0]);                            \
                    mma16816(acc[i][2 * j + 1], af[i], &bf[j][2]);                        \
                }                                                                         \
        }                                                                                 \
    }

    const int nch = 3 * (K >> 6);
    {
        int ka, kb;
        OFFS(0, ka, kb);
        COPY(0, ka, kb);
    }
    for (int ch = 0; ch < nch; ch++) {
        if (ch + 1 < nch) {
            int ka, kb;
            OFFS(ch + 1, ka, kb);
            COPY((ch + 1) & 1, ka, kb);
            asm volatile("cp.async.wait_group 1;" ::: "memory");
        } else {
            asm volatile("cp.async.wait_group 0;" ::: "memory");
        }
        __syncthreads();
        COMPUTE(ch & 1);
        __syncthreads();
    }

#pragma unroll
    for (int i = 0; i < 2; i++) {
#pragma unroll
        for (int j = 0; j < 8; j++) {
            int mA = m0 + wm + i * 16 + (lane >> 2);
            int col = n0 + wn + j * 8 + 2 * (lane & 3);
            if (EPI == 0) {
                if (mA < M) {
                    float2 v = make_float2(acc[i][j][0], acc[i][j][1]);
                    *(float2*)(C + (size_t)mA * ldc + col) = v;
                }
                if (mA + 8 < M) {
                    float2 v = make_float2(acc[i][j][2], acc[i][j][3]);
                    *(float2*)(C + (size_t)(mA + 8) * ldc + col) = v;
                }
            } else {
#pragma unroll
                for (int hh = 0; hh < 2; hh++) {
                    int m = mA + 8 * hh;
                    if (m < M) {
                        float sc = rsp[m];
                        float v0 = acc[i][j][2 * hh] * sc;
                        float v1 = acc[i][j][2 * hh + 1] * sc;
                        __nv_bfloat16 h0 = __float2bfloat16(v0);
                        __nv_bfloat16 h1 = __float2bfloat16(v1);
                        float l0 = v0 - __bfloat162float(h0);
                        float l1 = v1 - __bfloat162float(h1);
                        size_t base = (size_t)m * ldc + col0 + col;
                        outb[base >> 1] = __nv_bfloat162(h0, h1);
                        outb[(base + (ldc >> 1)) >> 1] =
                            __nv_bfloat162(__float2bfloat16(l0), __float2bfloat16(l1));
                    }
                }
            }
        }
    }
#undef OFFS
#undef COPY
#undef COMPUTE
}

// ---------------- single-type CSR gather (fp32 msgs, dst norm + next-layer emit) ----
__global__ __launch_bounds__(256) void gather_one_kernel(
    const float4* __restrict__ msg,
    const int* __restrict__ off, const int* __restrict__ csr,
    const float* __restrict__ rd, const float* __restrict__ rsn,
    float4* __restrict__ out, __nv_bfloat162* __restrict__ a2, int emit) {
    int node = blockIdx.x * 4 + (threadIdx.x >> 6);
    int c = threadIdx.x & 63;
    if (node >= N_SPOT) return;
    int b = off[node], e = off[node + 1];
    float4 acc = make_float4(0.f, 0.f, 0.f, 0.f);
#define ACCUM(sid)                                                       \
    {                                                                    \
        float4 v = __ldg(&msg[(size_t)(sid) * 64 + c]);                  \
        acc.x += v.x; acc.y += v.y; acc.z += v.z; acc.w += v.w;          \
    }
    int i = b;
    for (; i + 8 <= e; i += 8) {
        int s0 = __ldg(&csr[i]), s1 = __ldg(&csr[i + 1]);
        int s2 = __ldg(&csr[i + 2]), s3 = __ldg(&csr[i + 3]);
        int s4 = __ldg(&csr[i + 4]), s5 = __ldg(&csr[i + 5]);
        int s6 = __ldg(&csr[i + 6]), s7 = __ldg(&csr[i + 7]);
        ACCUM(s0) ACCUM(s1) ACCUM(s2) ACCUM(s3)
        ACCUM(s4) ACCUM(s5) ACCUM(s6) ACCUM(s7)
    }
    for (; i < e; i++) {
        int s0 = __ldg(&csr[i]);
        ACCUM(s0)
    }
#undef ACCUM
    float sc = rd[node];
    acc.x *= sc; acc.y *= sc; acc.z *= sc; acc.w *= sc;
    out[(size_t)node * 64 + c] = acc;

    if (emit) {
        float s2c = rsn[node];
        float vx = fmaxf(acc.x, 0.f) * s2c, vy = fmaxf(acc.y, 0.f) * s2c;
        float vz = fmaxf(acc.z, 0.f) * s2c, vw = fmaxf(acc.w, 0.f) * s2c;
        __nv_bfloat16 hx = __float2bfloat16(vx), hy = __float2bfloat16(vy);
        __nv_bfloat16 hz = __float2bfloat16(vz), hw = __float2bfloat16(vw);
        float rx = vx - __bfloat162float(hx), ry = vy - __bfloat162float(hy);
        float rz = vz - __bfloat162float(hz), rw = vw - __bfloat162float(hw);
        size_t bb = (size_t)node * 256 + 2 * c;
        a2[bb + 0] = __nv_bfloat162(hx, hy);
        a2[bb + 1] = __nv_bfloat162(hz, hw);
        a2[bb + 128 + 0] = __nv_bfloat162(__float2bfloat16(rx), __float2bfloat16(ry));
        a2[bb + 128 + 1] = __nv_bfloat162(__float2bfloat16(rz), __float2bfloat16(rw));
    }
}

// ---------------- outputs ----------------
__global__ void mean_kernel(const float4* __restrict__ s0, const float4* __restrict__ s1,
                            const float4* __restrict__ s2,
                            const float4* __restrict__ u0, const float4* __restrict__ u1,
                            const float4* __restrict__ u2,
                            float4* __restrict__ out, int n4) {
    int i = blockIdx.x * blockDim.x + threadIdx.x;
    if (i < n4) {
        const float r = 1.f / 3.f;
        float4 a = s0[i], b = s1[i], c = s2[i];
        float4 o;
        o.x = (fmaxf(a.x, 0.f) + fmaxf(b.x, 0.f) + fmaxf(c.x, 0.f)) * r;
        o.y = (fmaxf(a.y, 0.f) + fmaxf(b.y, 0.f) + fmaxf(c.y, 0.f)) * r;
        o.z = (fmaxf(a.z, 0.f) + fmaxf(b.z, 0.f) + fmaxf(c.z, 0.f)) * r;
        o.w = (fmaxf(a.w, 0.f) + fmaxf(b.w, 0.f) + fmaxf(c.w, 0.f)) * r;
        out[i] = o;
        a = u0[i]; b = u1[i]; c = u2[i];
        o.x = (fmaxf(a.x, 0.f) + fmaxf(b.x, 0.f) + fmaxf(c.x, 0.f)) * r;
        o.y = (fmaxf(a.y, 0.f) + fmaxf(b.y, 0.f) + fmaxf(c.y, 0.f)) * r;
        o.z = (fmaxf(a.z, 0.f) + fmaxf(b.z, 0.f) + fmaxf(c.z, 0.f)) * r;
        o.w = (fmaxf(a.w, 0.f) + fmaxf(b.w, 0.f) + fmaxf(c.w, 0.f)) * r;
        out[n4 + i] = o;
    }
}

__global__ void out_head_kernel(const float* __restrict__ hs, const float* __restrict__ hu,
                                const float* __restrict__ Ws, const float* __restrict__ bs,
                                const float* __restrict__ Wu, const float* __restrict__ bu,
                                float* __restrict__ out_s, float* __restrict__ out_u) {
    int warp = (blockIdx.x * blockDim.x + threadIdx.x) >> 5;
    int lane = threadIdx.x & 31;
    if (warp < N_SPOT) {
        const float* x = hs + (size_t)warp * HID;
        float s = 0.f;
#pragma unroll
        for (int i = lane; i < HID; i += 32) s += fmaxf(x[i], 0.f) * Ws[i];
#pragma unroll
        for (int o = 16; o; o >>= 1) s += __shfl_down_sync(0xffffffffu, s, o);
        if (lane == 0) out_s[warp] = s + bs[0];
    } else if (warp < 2 * N_SPOT) {
        int n = warp - N_SPOT;
        const float* x = hu + (size_t)n * HID;
        float s = 0.f;
#pragma unroll
        for (int i = lane; i < HID; i += 32) s += fmaxf(x[i], 0.f) * Wu[i];
#pragma unroll
        for (int o = 16; o; o >>= 1) s += __shfl_down_sync(0xffffffffu, s, o);
        if (lane == 0) out_u[n] = s + bu[0];
    }
}

// ---------------- host ----------------
static float* sym_addr(const void* sym) {
    void* p = nullptr;
    cudaGetSymbolAddress(&p, sym);
    return (float*)p;
}
static int* sym_addr_i(const void* sym) {
    void* p = nullptr;
    cudaGetSymbolAddress(&p, sym);
    return (int*)p;
}
static __nv_bfloat16* sym_addr_b(const void* sym) {
    void* p = nullptr;
    cudaGetSymbolAddress(&p, sym);
    return (__nv_bfloat16*)p;
}

extern "C" void kernel_launch(void* const* d_in, const int* in_sizes, int n_in,
                              void* d_out, int out_size) {
    const float* x_spot  = (const float*)d_in[0];
    const float* x_user  = (const float*)d_in[1];
    const int*   edge_us = (const int*)d_in[2];
    const int*   edge_su = (const int*)d_in[3];
    const float* W_att   = (const float*)d_in[4];
    const float* q_att   = (const float*)d_in[5];
    const float* W0_us   = (const float*)d_in[6];
    const float* W0_su   = (const float*)d_in[7];
    const float* Wmid_us = (const float*)d_in[8];
    const float* Wmid_su = (const float*)d_in[9];
    const float* W_out_s = (const float*)d_in[10];
    const float* b_out_s = (const float*)d_in[11];
    const float* W_out_u = (const float*)d_in[12];
    const float* b_out_u = (const float*)d_in[13];
    float* out = (float*)d_out;

    float* p_wq    = sym_addr(g_wq);
    float* p_tmp_u = sym_addr(g_tmp_u);
    float* p_tmp_s = sym_addr(g_tmp_s);
    float* p_hs    = sym_addr(g_hs);
    float* p_hu    = sym_addr(g_hu);
    float* p_deg   = sym_addr(g_deg);
    float* p_rs    = sym_addr(g_rs);
    int* p_off_us  = sym_addr_i(g_off_us);
    int* p_cur_us  = sym_addr_i(g_cur_us);
    int* p_csr_us  = sym_addr_i(g_csr_us);
    int* p_off_su  = sym_addr_i(g_off_su);
    int* p_cur_su  = sym_addr_i(g_cur_su);
    int* p_csr_su  = sym_addr_i(g_csr_su);
    __nv_bfloat16* p_A2att = sym_addr_b(g_A2att);
    __nv_bfloat16* p_Au2   = sym_addr_b(g_Au2);  // 2 consecutive buffers
    __nv_bfloat16* p_As2   = sym_addr_b(g_As2);
    __nv_bfloat16* p_B2    = sym_addr_b(g_B2);
    const size_t ABUF = (size_t)MPAD * 1024;
    __nv_bfloat16* Au[2] = {p_Au2, p_Au2 + ABUF};
    __nv_bfloat16* As[2] = {p_As2, p_As2 + ABUF};

    static cudaStream_t s1 = nullptr, sB = nullptr;
    static cudaEvent_t e0, eRS, eCSR, eWP, eTU0, eTS0, eGS0, eGS1, eGS2, eGU0, eGU1;
    if (!s1) {
        cudaStreamCreateWithFlags(&s1, cudaStreamNonBlocking);
        cudaStreamCreateWithFlags(&sB, cudaStreamNonBlocking);
        cudaEventCreateWithFlags(&e0, cudaEventDisableTiming);
        cudaEventCreateWithFlags(&eRS, cudaEventDisableTiming);
        cudaEventCreateWithFlags(&eCSR, cudaEventDisableTiming);
        cudaEventCreateWithFlags(&eWP, cudaEventDisableTiming);
        cudaEventCreateWithFlags(&eTU0, cudaEventDisableTiming);
        cudaEventCreateWithFlags(&eTS0, cudaEventDisableTiming);
        cudaEventCreateWithFlags(&eGS0, cudaEventDisableTiming);
        cudaEventCreateWithFlags(&eGS1, cudaEventDisableTiming);
        cudaEventCreateWithFlags(&eGS2, cudaEventDisableTiming);
        cudaEventCreateWithFlags(&eGU0, cudaEventDisableTiming);
        cudaEventCreateWithFlags(&eGU1, cudaEventDisableTiming);
    }

    const size_t HN = (size_t)N_SPOT * HID;
    const int NHID = N_SPOT * HID;
    const int SMEM = STG * 36864;  // 73728
    cudaFuncSetAttribute(hmma_gemm<0>, cudaFuncAttributeMaxDynamicSharedMemorySize, SMEM);
    cudaFuncSetAttribute(hmma_gemm<1>, cudaFuncAttributeMaxDynamicSharedMemorySize, SMEM);

    int eb = (NE + 255) / 256;
    int gb1 = (N_SPOT + 3) / 4;
    int rb = (NHID / 4 + 255) / 256;
    dim3 ggemm(MPAD / 128, 2, 1);

    // ---- fork ----
    cudaEventRecord(e0, 0);
    cudaStreamWaitEvent(s1, e0, 0);
    cudaStreamWaitEvent(sB, e0, 0);

    // s1: prep chain
    cudaMemsetAsync(p_deg, 0, 4 * N_SPOT * sizeof(float), s1);
    deg_count_kernel<<<eb, 256, 0, s1>>>(edge_us, edge_su, p_deg);
    rsqrt_kernel<<<(4 * N_SPOT + 255) / 256, 256, 0, s1>>>(p_deg, p_rs);
    cudaEventRecord(eRS, s1);
    scan2_kernel<<<2, 1024, 0, s1>>>(p_deg, p_off_us, p_cur_us, p_off_su, p_cur_su);
    fill_both_kernel<<<eb, 256, 0, s1>>>(edge_us, edge_su, p_cur_us, p_csr_us,
                                         p_cur_su, p_csr_su);
    cudaEventRecord(eCSR, s1);

    // origin: weights + attention pooling
    wq_kernel<<<(HEADS * ATT_IN + 255) / 256, 256>>>(W_att, q_att, p_wq);
    wprep_all_kernel<<<3072, 256>>>(W_att, W0_us, W0_su, Wmid_us, Wmid_su, p_B2);
    cudaEventRecord(eWP, 0);
    att_kernel<<<N_SPOT, 128>>>(x_spot, p_wq, p_A2att);

    // sB: user chain start
    cudaStreamWaitEvent(sB, eRS, 0);
    aconv_kernel<<<(MPAD * 128 + 255) / 256, 256, 0, sB>>>(
        (const float4*)x_user, p_rs + 0 * N_SPOT, N_USER, 128, MPAD,
        (__nv_bfloat162*)Au[0]);
    cudaStreamWaitEvent(sB, eWP, 0);
    hmma_gemm<0><<<ggemm, 256, SMEM, sB>>>(
        Au[0], 1024, p_B2 + WOFF_L0US, 1024, p_tmp_u, nullptr, nullptr,
        HID, N_USER, 512, 0, 0, 0);
    cudaEventRecord(eTU0, sB);
    cudaStreamWaitEvent(sB, eCSR, 0);
    gather_one_kernel<<<gb1, 256, 0, sB>>>(
        (const float4*)p_tmp_u, p_off_us, p_csr_us,
        p_rs + 1 * N_SPOT, p_rs + 2 * N_SPOT,
        (float4*)p_hs, (__nv_bfloat162*)As[1], 1);
    cudaEventRecord(eGS0, sB);

    // origin: spot chain start
    cudaStreamWaitEvent(0, eRS, 0);
    hmma_gemm<1><<<dim3(MPAD / 128, 1, HEADS), 256, SMEM>>>(
        p_A2att, 1024, p_B2 + WOFF_ATT, 1024, nullptr,
        (__nv_bfloat162*)As[0], p_rs + 2 * N_SPOT,
        1024, N_SPOT, 512,
        (long)MPAD * 1024, (long)128 * 1024, 128);
    hmma_gemm<0><<<ggemm, 256, SMEM>>>(
        As[0], 1024, p_B2 + WOFF_L0SU, 1024, p_tmp_s, nullptr, nullptr,
        HID, N_SPOT, 512, 0, 0, 0);
    cudaEventRecord(eTS0, 0);
    cudaStreamWaitEvent(0, eCSR, 0);
    gather_one_kernel<<<gb1, 256>>>(
        (const float4*)p_tmp_s, p_off_su, p_csr_su,
        p_rs + 3 * N_SPOT, p_rs + 0 * N_SPOT,
        (float4*)p_hu, (__nv_bfloat162*)Au[1], 1);
    cudaEventRecord(eGU0, 0);

    // layer 1
    cudaStreamWaitEvent(sB, eGU0, 0);
    hmma_gemm<0><<<ggemm, 256, SMEM, sB>>>(
        Au[1], 512, p_B2 + WOFF_MUS + 0 * 131072, 512, p_tmp_u, nullptr, nullptr,
        HID, N_USER, 256, 0, 0, 0);
    cudaStreamWaitEvent(sB, eTS0, 0);
    gather_one_kernel<<<gb1, 256, 0, sB>>>(
        (const float4*)p_tmp_u, p_off_us, p_csr_us,
        p_rs + 1 * N_SPOT, p_rs + 2 * N_SPOT,
        (float4*)(p_hs + HN), (__nv_bfloat162*)As[0], 1);
    cudaEventRecord(eGS1, sB);

    cudaStreamWaitEvent(0, eGS0, 0);
    hmma_gemm<0><<<ggemm, 256, SMEM>>>(
        As[1], 512, p_B2 + WOFF_MSU + 0 * 131072, 512, p_tmp_s, nullptr, nullptr,
        HID, N_SPOT, 256, 0, 0, 0);
    cudaStreamWaitEvent(0, eTU0, 0);
    gather_one_kernel<<<gb1, 256>>>(
        (const float4*)p_tmp_s, p_off_su, p_csr_su,
        p_rs + 3 * N_SPOT, p_rs + 0 * N_SPOT,
        (float4*)(p_hu + HN), (__nv_bfloat162*)Au[0], 1);
    cudaEventRecord(eGU1, 0);

    // layer 2
    cudaStreamWaitEvent(sB, eGU1, 0);
    hmma_gemm<0><<<ggemm, 256, SMEM, sB>>>(
        Au[0], 512, p_B2 + WOFF_MUS + 1 * 131072, 512, p_tmp_u, nullptr, nullptr,
        HID, N_USER, 256, 0, 0, 0);
    gather_one_kernel<<<gb1, 256, 0, sB>>>(
        (const float4*)p_tmp_u, p_off_us, p_csr_us,
        p_rs + 1 * N_SPOT, p_rs + 2 * N_SPOT,
        (float4*)(p_hs + 2 * HN), nullptr, 0);
    cudaEventRecord(eGS2, sB);

    cudaStreamWaitEvent(0, eGS1, 0);
    hmma_gemm<0><<<ggemm, 256, SMEM>>>(
        As[0], 512, p_B2 + WOFF_MSU + 1 * 131072, 512, p_tmp_s, nullptr, nullptr,
        HID, N_SPOT, 256, 0, 0, 0);
    gather_one_kernel<<<gb1, 256>>>(
        (const float4*)p_tmp_s, p_off_su, p_csr_su,
        p_rs + 3 * N_SPOT, p_rs + 0 * N_SPOT,
        (float4*)(p_hu + 2 * HN), nullptr, 0);

    // outputs (join sB)
    cudaStreamWaitEvent(0, eGS2, 0);
    mean_kernel<<<rb, 256>>>((const float4*)p_hs, (const float4*)(p_hs + HN),
                             (const float4*)(p_hs + 2 * HN),
                             (const float4*)p_hu, (const float4*)(p_hu + HN),
                             (const float4*)(p_hu + 2 * HN),
                             (float4*)out, NHID / 4);
    out_head_kernel<<<(2 * N_SPOT * 32 + 255) / 256, 256>>>(
        p_hs + 2 * HN, p_hu + 2 * HN, W_out_s, b_out_s, W_out_u, b_out_u,
        out + 2 * (size_t)NHID, out + 2 * (size_t)NHID + N_SPOT);
}